// round 2
// baseline (speedup 1.0000x reference)
#include <cuda_runtime.h>
#include <cstdint>
#include <math.h>
#include <cub/cub.cuh>

// ============================================================================
// Problem constants
// ============================================================================
#define MAXN    1048576
#define NSTEPS  8
#define HALFB   1024      // blocks per role; total grid = 2*HALFB
#define GNT     128       // threads per block

struct SubKeys { unsigned k0[NSTEPS]; unsigned k1[NSTEPS]; };

// ============================================================================
// Static device scratch (no dynamic allocation allowed)
// ============================================================================
__device__ __align__(256) unsigned      g_keysA[NSTEPS * MAXN];
__device__ __align__(256) unsigned      g_keysB[NSTEPS * MAXN];
__device__ __align__(256) unsigned      g_valsA[NSTEPS * MAXN];
__device__ __align__(256) unsigned      g_valsB[NSTEPS * MAXN];
__device__ __align__(256) unsigned char g_cubtmp[64u << 20];

__device__ float  g_P[73];                    // [0..63]=w1, [64..67]=b1, [68..71]=w2, [72]=b2
__device__ float  g_m[73];
__device__ float  g_v[73];
__device__ float  g_partial[2][73][HALFB];    // unnormalized grad partials per role/param/block
__device__ double g_S[2][HALFB];              // unnormalized softmax sums per role/block
__device__ double g_G[2][73];
__device__ float  g_losses[NSTEPS];

// ============================================================================
// Threefry2x32 — exact JAX implementation (20 rounds, 5 key injections)
// ============================================================================
__host__ __device__ __forceinline__ void tf2x32(unsigned k0, unsigned k1,
                                                unsigned c0, unsigned c1,
                                                unsigned &o0, unsigned &o1) {
    unsigned ks0 = k0, ks1 = k1, ks2 = k0 ^ k1 ^ 0x1BD11BDAu;
    unsigned x0 = c0 + ks0, x1 = c1 + ks1;
#define TFR(r) { x0 += x1; x1 = (x1 << (r)) | (x1 >> (32 - (r))); x1 ^= x0; }
    TFR(13) TFR(15) TFR(26) TFR(6)
    x0 += ks1; x1 += ks2 + 1u;
    TFR(17) TFR(29) TFR(16) TFR(24)
    x0 += ks2; x1 += ks0 + 2u;
    TFR(13) TFR(15) TFR(26) TFR(6)
    x0 += ks0; x1 += ks1 + 3u;
    TFR(17) TFR(29) TFR(16) TFR(24)
    x0 += ks1; x1 += ks2 + 4u;
    TFR(13) TFR(15) TFR(26) TFR(6)
    x0 += ks2; x1 += ks0 + 5u;
#undef TFR
    o0 = x0; o1 = x1;
}

// Random sort keys for one shuffle round of all NSTEPS permutations.
// Partitionable threefry 32-bit random_bits: bits[i] = x0 ^ x1 of enc(key,(0,i)).
__global__ void rmi_gen_keys(SubKeys sk, int N,
                             unsigned* __restrict__ keys,
                             unsigned* __restrict__ vals) {
    int total  = NSTEPS * N;
    int stride = gridDim.x * blockDim.x;
    for (int idx = blockIdx.x * blockDim.x + threadIdx.x; idx < total; idx += stride) {
        int g = idx / N;
        unsigned i = (unsigned)(idx - g * N);
        unsigned a, b;
        tf2x32(sk.k0[g], sk.k1[g], 0u, i, a, b);
        keys[idx] = a ^ b;
        if (vals) vals[idx] = i;
    }
}

// ============================================================================
// Parameter init
// ============================================================================
__global__ void rmi_init_params(const float* __restrict__ w1,
                                const float* __restrict__ b1,
                                const float* __restrict__ w2,
                                const float* __restrict__ b2) {
    int t = threadIdx.x;
    if (t < 64)       g_P[t] = w1[t];
    else if (t < 68)  g_P[t] = b1[t - 64];
    else if (t < 72)  g_P[t] = w2[t - 68];
    else if (t == 72) g_P[72] = b2[0];
    if (t < 73) { g_m[t] = 0.f; g_v[t] = 0.f; }
}

// ============================================================================
// Tiny-MLP helpers
// ============================================================================
__device__ __forceinline__ void load8(const float* __restrict__ base, unsigned row,
                                      float* __restrict__ dst) {
    const float4* p = (const float4*)base + 2ull * row;
    float4 a = __ldg(p), b = __ldg(p + 1);
    dst[0] = a.x; dst[1] = a.y; dst[2] = a.z; dst[3] = a.w;
    dst[4] = b.x; dst[5] = b.y; dst[6] = b.z; dst[7] = b.w;
}

__device__ __forceinline__ float fwd_eval(const float* __restrict__ inp,
                                          const float* __restrict__ P,
                                          float* __restrict__ h) {
    float s = P[72];
#pragma unroll
    for (int k = 0; k < 4; k++) {
        float u = P[64 + k];
#pragma unroll
        for (int j = 0; j < 16; j++) u = fmaf(P[k * 16 + j], inp[j], u);
        float hk = tanhf(u);
        h[k] = hk;
        s = fmaf(P[68 + k], hk, s);
    }
    return tanhf(s);
}

__device__ __forceinline__ void acc_grad(const float* __restrict__ inp,
                                         const float* __restrict__ h,
                                         float o, float wgt,
                                         const float* __restrict__ P,
                                         float* __restrict__ acc) {
    float d = wgt * (1.f - o * o);
    acc[72] += d;
#pragma unroll
    for (int k = 0; k < 4; k++) {
        acc[68 + k] = fmaf(d, h[k], acc[68 + k]);
        float e = d * P[68 + k] * (1.f - h[k] * h[k]);
        acc[64 + k] += e;
#pragma unroll
        for (int j = 0; j < 16; j++)
            acc[k * 16 + j] = fmaf(e, inp[j], acc[k * 16 + j]);
    }
}

// ============================================================================
// Fused per-step pass: role 0 -> (S1, G1) over (x_i, y_i);
//                      role 1 -> (S2, G2) over (x_i, y_{pi_i}) with f2 = 2*o.
// Unnormalized accumulation; normalization happens in finalize.
// Interleaved roles (blockIdx&1) so both roles stream the same x range -> L2 reuse.
// ============================================================================
__global__ void __launch_bounds__(GNT, 4)
rmi_fused_step(const float* __restrict__ x, const float* __restrict__ y,
               const unsigned* __restrict__ pi, int N) {
    const int role = blockIdx.x & 1;
    const int b    = blockIdx.x >> 1;

    __shared__ float Ps[73];
    if (threadIdx.x < 73) Ps[threadIdx.x] = g_P[threadIdx.x];
    __syncthreads();

    float acc[73];
#pragma unroll
    for (int t = 0; t < 73; t++) acc[t] = 0.f;
    float S = 0.f;

    const int stride = HALFB * GNT;
    for (int i = b * GNT + threadIdx.x; i < N; i += stride) {
        float inp[16], h[4];
        load8(x, (unsigned)i, inp);
        unsigned row = role ? __ldg(pi + i) : (unsigned)i;
        load8(y, row, inp + 8);
        float o = fwd_eval(inp, Ps, h);
        float f = role ? 2.f * o : o;       // ALPHA=2: f2 = 2*est, f1 = est
        float w = expf(f);                  // no shift needed: |f| <= 2
        S += w;
        acc_grad(inp, h, o, w, Ps, acc);
    }

    // --- deterministic block reduction of 73 accumulators ---
#pragma unroll
    for (int t = 0; t < 73; t++) {
        float v = acc[t];
#pragma unroll
        for (int o = 16; o > 0; o >>= 1) v += __shfl_down_sync(0xffffffffu, v, o);
        acc[t] = v;
    }
    __shared__ float wsum[GNT / 32][73];
    int wid = threadIdx.x >> 5, lane = threadIdx.x & 31;
    if (lane == 0) {
#pragma unroll
        for (int t = 0; t < 73; t++) wsum[wid][t] = acc[t];
    }
    __syncthreads();
    if (threadIdx.x < 73) {
        float s = 0.f;
#pragma unroll
        for (int w = 0; w < GNT / 32; w++) s += wsum[w][threadIdx.x];
        g_partial[role][threadIdx.x][b] = s;
    }

    // --- deterministic block reduction of S (fp64 tree) ---
    __shared__ double red[GNT];
    red[threadIdx.x] = (double)S;
    __syncthreads();
    for (int o = GNT / 2; o > 0; o >>= 1) {
        if (threadIdx.x < (unsigned)o) red[threadIdx.x] += red[threadIdx.x + o];
        __syncthreads();
    }
    if (threadIdx.x == 0) g_S[role][b] = red[0];
}

// ============================================================================
// Finalize: S totals, loss, grad normalization, Adam. One block, 1024 threads.
// All reductions fixed-shape -> bit-deterministic across replays.
// ============================================================================
__global__ void __launch_bounds__(1024)
rmi_finalize(int step, float bc1, float bc2, double logN) {
    __shared__ double red[256];
    __shared__ double sS[2];

    // Phase 1: S1, S2 (threads 0..255; 128 per role; strided fp64 + tree)
    if (threadIdx.x < 256) {
        int role = threadIdx.x >> 7;
        int lane = threadIdx.x & 127;
        double s = 0.0;
        for (int bb = lane; bb < HALFB; bb += 128) s += g_S[role][bb];
        red[threadIdx.x] = s;
    }
    __syncthreads();
    for (int o = 64; o > 0; o >>= 1) {
        if (threadIdx.x < 256 && (threadIdx.x & 127) < o)
            red[threadIdx.x] += red[threadIdx.x + o];
        __syncthreads();
    }
    if (threadIdx.x == 0)   sS[0] = red[0];
    if (threadIdx.x == 128) sS[1] = red[128];
    __syncthreads();
    double S1 = sS[0], S2 = sS[1];

    // Phase 2: per-param grad sums over HALFB blocks (one warp per row)
    int wid = threadIdx.x >> 5, lane = threadIdx.x & 31;
    for (int row = wid; row < 146; row += 32) {
        int role = row >= 73 ? 1 : 0;
        int p = role ? row - 73 : row;
        const float* src = &g_partial[role][p][0];
        double s = 0.0;
        for (int bb = lane; bb < HALFB; bb += 32) s += (double)__ldg(src + bb);
#pragma unroll
        for (int o = 16; o > 0; o >>= 1) s += __shfl_down_sync(0xffffffffu, s, o);
        if (lane == 0) g_G[role][p] = s;
    }
    __syncthreads();

    // Phase 3: loss + Adam
    if (threadIdx.x == 0) {
        double t1 = log(S1) - logN;              // lse(f1) - logN
        double t2 = 0.5 * (log(S2) - logN);      // (lse(f2) - logN)/ALPHA
        g_losses[step] = (float)(t1 - t2);
    }
    if (threadIdx.x < 73) {
        int t = threadIdx.x;
        float g = (float)(g_G[1][t] / S2 - g_G[0][t] / S1);
        float m = 0.9f   * g_m[t] + 0.1f   * g;
        float v = 0.999f * g_v[t] + 0.001f * g * g;
        g_m[t] = m; g_v[t] = v;
        g_P[t] -= 1e-3f * (m / bc1) / (sqrtf(v / bc2) + 1e-8f);
    }
}

// ============================================================================
// Output: reference returns (losses[-1], losses) -> 9 floats (or 8 / 1)
// ============================================================================
__global__ void rmi_write_out(float* __restrict__ out, int out_size) {
    for (int i = threadIdx.x; i < out_size; i += blockDim.x) {
        float v;
        if (out_size == NSTEPS)      v = g_losses[i];
        else if (out_size == 1)      v = g_losses[NSTEPS - 1];
        else {
            if (i == 0)              v = g_losses[NSTEPS - 1];
            else if (i <= NSTEPS)    v = g_losses[i - 1];
            else                     v = 0.f;
        }
        out[i] = v;
    }
}

// ============================================================================
// Host driver (graph-capturable: kernel launches + CUB sorts only)
// ============================================================================
extern "C" void kernel_launch(void* const* d_in, const int* in_sizes, int n_in,
                              void* d_out, int out_size) {
    const float* x  = (const float*)d_in[0];
    const float* y  = (const float*)d_in[1];
    const float* w1 = (const float*)d_in[2];
    const float* b1 = (const float*)d_in[3];
    const float* w2 = (const float*)d_in[4];
    const float* b2 = (const float*)d_in[5];
    int N = in_sizes[0] / 8;
    if (N > MAXN) N = MAXN;

    rmi_init_params<<<1, 128>>>(w1, b1, w2, b2);

    // --- shuffle subkeys (host, input-independent, deterministic) ---
    // master key(42) = (0,42); fold-like split: key_s = tf(master,(0,s));
    // per round: new_key = tf(K,(0,0)), subkey = tf(K,(0,1)).
    int rounds = (int)ceil(3.0 * log((double)N) / log(4294967295.0));
    if (rounds < 1) rounds = 1;
    if (rounds > 4) rounds = 4;

    SubKeys subk[4];
    for (int s = 0; s < NSTEPS; s++) {
        unsigned K0, K1;
        tf2x32(0u, 42u, 0u, (unsigned)s, K0, K1);
        for (int r = 0; r < rounds; r++) {
            unsigned nk0, nk1, sb0, sb1;
            tf2x32(K0, K1, 0u, 0u, nk0, nk1);
            tf2x32(K0, K1, 0u, 1u, sb0, sb1);
            subk[r].k0[s] = sb0; subk[r].k1[s] = sb1;
            K0 = nk0; K1 = nk1;
        }
    }

    unsigned *kA, *kB, *vA, *vB; void* tmp;
    cudaGetSymbolAddress((void**)&kA, g_keysA);
    cudaGetSymbolAddress((void**)&kB, g_keysB);
    cudaGetSymbolAddress((void**)&vA, g_valsA);
    cudaGetSymbolAddress((void**)&vB, g_valsB);
    cudaGetSymbolAddress(&tmp, g_cubtmp);

    // Segmented stable radix sorts: per round, 8 independent 32-bit sorts.
    unsigned *vcur = vA, *valt = vB;
    for (int r = 0; r < rounds; r++) {
        rmi_gen_keys<<<4096, 256>>>(subk[r], N, kA,
                                    r == 0 ? vcur : (unsigned*)nullptr);
        int endsel = 0;
        for (int g = 0; g < NSTEPS; g++) {
            size_t off = (size_t)g * N;
            cub::DoubleBuffer<unsigned> dk(kA + off, kB + off);
            cub::DoubleBuffer<unsigned> dv(vcur + off, valt + off);
            size_t bytes = sizeof(g_cubtmp);
            cub::DeviceRadixSort::SortPairs(tmp, bytes, dk, dv, N, 0, 32);
            endsel = dv.selector;
        }
        if (endsel == 1) { unsigned* t = vcur; vcur = valt; valt = t; }
    }
    const unsigned* perms = vcur;

    // --- 8 fused training steps ---
    const double logN = log((double)N);
    for (int s = 0; s < NSTEPS; s++) {
        const unsigned* pi = perms + (size_t)s * N;
        rmi_fused_step<<<2 * HALFB, GNT>>>(x, y, pi, N);
        double t = (double)(s + 1);
        float bc1 = (float)(1.0 - pow(0.9,   t));
        float bc2 = (float)(1.0 - pow(0.999, t));
        rmi_finalize<<<1, 1024>>>(s, bc1, bc2, logN);
    }

    rmi_write_out<<<1, 32>>>((float*)d_out, out_size);
}

// round 3
// speedup vs baseline: 1.1615x; 1.1615x over previous
#include <cuda_runtime.h>
#include <cstdint>
#include <math.h>
#include <cub/cub.cuh>

// ============================================================================
// Problem constants
// ============================================================================
#define MAXN    1048576
#define NSTEPS  8
#define HALFB   1024      // blocks per role; total grid = 2*HALFB
#define GNT     128       // threads per block

struct SubKeys { unsigned k0[NSTEPS]; unsigned k1[NSTEPS]; };

// ============================================================================
// Static device scratch (no dynamic allocation allowed)
// ============================================================================
__device__ __align__(256) unsigned long long g_keysA[NSTEPS * MAXN];
__device__ __align__(256) unsigned long long g_keysB[NSTEPS * MAXN];
__device__ __align__(256) unsigned           g_valsA[NSTEPS * MAXN];
__device__ __align__(256) unsigned           g_valsB[NSTEPS * MAXN];
__device__ __align__(256) unsigned char      g_cubtmp[64u << 20];

__device__ float  g_P[73];                    // [0..63]=w1, [64..67]=b1, [68..71]=w2, [72]=b2
__device__ float  g_m[73];
__device__ float  g_v[73];
__device__ float  g_partial[2][73][HALFB];    // unnormalized grad partials per role/param/block
__device__ double g_S[2][HALFB];              // unnormalized softmax sums per role/block
__device__ double g_G[2][73];
__device__ float  g_losses[NSTEPS];

// ============================================================================
// Threefry2x32 — exact JAX implementation (20 rounds, 5 key injections)
// ============================================================================
__host__ __device__ __forceinline__ void tf2x32(unsigned k0, unsigned k1,
                                                unsigned c0, unsigned c1,
                                                unsigned &o0, unsigned &o1) {
    unsigned ks0 = k0, ks1 = k1, ks2 = k0 ^ k1 ^ 0x1BD11BDAu;
    unsigned x0 = c0 + ks0, x1 = c1 + ks1;
#define TFR(r) { x0 += x1; x1 = (x1 << (r)) | (x1 >> (32 - (r))); x1 ^= x0; }
    TFR(13) TFR(15) TFR(26) TFR(6)
    x0 += ks1; x1 += ks2 + 1u;
    TFR(17) TFR(29) TFR(16) TFR(24)
    x0 += ks2; x1 += ks0 + 2u;
    TFR(13) TFR(15) TFR(26) TFR(6)
    x0 += ks0; x1 += ks1 + 3u;
    TFR(17) TFR(29) TFR(16) TFR(24)
    x0 += ks1; x1 += ks2 + 4u;
    TFR(13) TFR(15) TFR(26) TFR(6)
    x0 += ks2; x1 += ks0 + 5u;
#undef TFR
    o0 = x0; o1 = x1;
}

// Random sort keys for one shuffle round of all NSTEPS permutations.
// Partitionable threefry 32-bit random_bits: bits[i] = x0 ^ x1 of enc(key,(0,i)).
// Composite 64-bit key (perm_id << 32) | bits -> one batched stable radix sort
// (bits [0,35)) handles all 8 permutations at full chip occupancy.
__global__ void rmi_gen_keys(SubKeys sk, int N,
                             unsigned long long* __restrict__ keys,
                             unsigned* __restrict__ vals) {
    long long total  = (long long)NSTEPS * N;
    long long stride = (long long)gridDim.x * blockDim.x;
    for (long long idx = (long long)blockIdx.x * blockDim.x + threadIdx.x;
         idx < total; idx += stride) {
        int g = (int)(idx / N);
        unsigned i = (unsigned)(idx - (long long)g * N);
        unsigned a, b;
        tf2x32(sk.k0[g], sk.k1[g], 0u, i, a, b);
        keys[idx] = ((unsigned long long)g << 32) | (unsigned long long)(a ^ b);
        if (vals) vals[idx] = i;
    }
}

// ============================================================================
// Parameter init
// ============================================================================
__global__ void rmi_init_params(const float* __restrict__ w1,
                                const float* __restrict__ b1,
                                const float* __restrict__ w2,
                                const float* __restrict__ b2) {
    int t = threadIdx.x;
    if (t < 64)       g_P[t] = w1[t];
    else if (t < 68)  g_P[t] = b1[t - 64];
    else if (t < 72)  g_P[t] = w2[t - 68];
    else if (t == 72) g_P[72] = b2[0];
    if (t < 73) { g_m[t] = 0.f; g_v[t] = 0.f; }
}

// ============================================================================
// Tiny-MLP helpers
// ============================================================================
__device__ __forceinline__ void load8(const float* __restrict__ base, unsigned row,
                                      float* __restrict__ dst) {
    const float4* p = (const float4*)base + 2ull * row;
    float4 a = __ldg(p), b = __ldg(p + 1);
    dst[0] = a.x; dst[1] = a.y; dst[2] = a.z; dst[3] = a.w;
    dst[4] = b.x; dst[5] = b.y; dst[6] = b.z; dst[7] = b.w;
}

__device__ __forceinline__ float fwd_eval(const float* __restrict__ inp,
                                          const float* __restrict__ P,
                                          float* __restrict__ h) {
    float s = P[72];
#pragma unroll
    for (int k = 0; k < 4; k++) {
        float u = P[64 + k];
#pragma unroll
        for (int j = 0; j < 16; j++) u = fmaf(P[k * 16 + j], inp[j], u);
        float hk = tanhf(u);
        h[k] = hk;
        s = fmaf(P[68 + k], hk, s);
    }
    return tanhf(s);
}

__device__ __forceinline__ void acc_grad(const float* __restrict__ inp,
                                         const float* __restrict__ h,
                                         float o, float wgt,
                                         const float* __restrict__ P,
                                         float* __restrict__ acc) {
    float d = wgt * (1.f - o * o);
    acc[72] += d;
#pragma unroll
    for (int k = 0; k < 4; k++) {
        acc[68 + k] = fmaf(d, h[k], acc[68 + k]);
        float e = d * P[68 + k] * (1.f - h[k] * h[k]);
        acc[64 + k] += e;
#pragma unroll
        for (int j = 0; j < 16; j++)
            acc[k * 16 + j] = fmaf(e, inp[j], acc[k * 16 + j]);
    }
}

// ============================================================================
// Fused per-step pass: role 0 -> (S1, G1) over (x_i, y_i);
//                      role 1 -> (S2, G2) over (x_i, y_{pi_i}) with f2 = 2*o.
// Unnormalized accumulation; normalization happens in finalize.
// Interleaved roles (blockIdx&1) so both roles stream the same x range -> L2 reuse.
// ============================================================================
__global__ void __launch_bounds__(GNT, 4)
rmi_fused_step(const float* __restrict__ x, const float* __restrict__ y,
               const unsigned* __restrict__ pi, int N) {
    const int role = blockIdx.x & 1;
    const int b    = blockIdx.x >> 1;

    __shared__ float Ps[73];
    if (threadIdx.x < 73) Ps[threadIdx.x] = g_P[threadIdx.x];
    __syncthreads();

    float acc[73];
#pragma unroll
    for (int t = 0; t < 73; t++) acc[t] = 0.f;
    float S = 0.f;

    const int stride = HALFB * GNT;
    for (int i = b * GNT + threadIdx.x; i < N; i += stride) {
        float inp[16], h[4];
        load8(x, (unsigned)i, inp);
        unsigned row = role ? __ldg(pi + i) : (unsigned)i;
        load8(y, row, inp + 8);
        float o = fwd_eval(inp, Ps, h);
        float f = role ? 2.f * o : o;       // ALPHA=2: f2 = 2*est, f1 = est
        float w = expf(f);                  // no shift needed: |f| <= 2
        S += w;
        acc_grad(inp, h, o, w, Ps, acc);
    }

    // --- deterministic block reduction of 73 accumulators ---
#pragma unroll
    for (int t = 0; t < 73; t++) {
        float v = acc[t];
#pragma unroll
        for (int o = 16; o > 0; o >>= 1) v += __shfl_down_sync(0xffffffffu, v, o);
        acc[t] = v;
    }
    __shared__ float wsum[GNT / 32][73];
    int wid = threadIdx.x >> 5, lane = threadIdx.x & 31;
    if (lane == 0) {
#pragma unroll
        for (int t = 0; t < 73; t++) wsum[wid][t] = acc[t];
    }
    __syncthreads();
    if (threadIdx.x < 73) {
        float s = 0.f;
#pragma unroll
        for (int w = 0; w < GNT / 32; w++) s += wsum[w][threadIdx.x];
        g_partial[role][threadIdx.x][b] = s;
    }

    // --- deterministic block reduction of S (fp64 tree) ---
    __shared__ double red[GNT];
    red[threadIdx.x] = (double)S;
    __syncthreads();
    for (int o = GNT / 2; o > 0; o >>= 1) {
        if (threadIdx.x < (unsigned)o) red[threadIdx.x] += red[threadIdx.x + o];
        __syncthreads();
    }
    if (threadIdx.x == 0) g_S[role][b] = red[0];
}

// ============================================================================
// Finalize: S totals, loss, grad normalization, Adam. One block, 1024 threads.
// All reductions fixed-shape -> bit-deterministic across replays.
// ============================================================================
__global__ void __launch_bounds__(1024)
rmi_finalize(int step, float bc1, float bc2, double logN) {
    __shared__ double red[256];
    __shared__ double sS[2];

    // Phase 1: S1, S2 (threads 0..255; 128 per role; strided fp64 + tree)
    if (threadIdx.x < 256) {
        int role = threadIdx.x >> 7;
        int lane = threadIdx.x & 127;
        double s = 0.0;
        for (int bb = lane; bb < HALFB; bb += 128) s += g_S[role][bb];
        red[threadIdx.x] = s;
    }
    __syncthreads();
    for (int o = 64; o > 0; o >>= 1) {
        if (threadIdx.x < 256 && (threadIdx.x & 127) < o)
            red[threadIdx.x] += red[threadIdx.x + o];
        __syncthreads();
    }
    if (threadIdx.x == 0)   sS[0] = red[0];
    if (threadIdx.x == 128) sS[1] = red[128];
    __syncthreads();
    double S1 = sS[0], S2 = sS[1];

    // Phase 2: per-param grad sums over HALFB blocks (one warp per row)
    int wid = threadIdx.x >> 5, lane = threadIdx.x & 31;
    for (int row = wid; row < 146; row += 32) {
        int role = row >= 73 ? 1 : 0;
        int p = role ? row - 73 : row;
        const float* src = &g_partial[role][p][0];
        double s = 0.0;
        for (int bb = lane; bb < HALFB; bb += 32) s += (double)__ldg(src + bb);
#pragma unroll
        for (int o = 16; o > 0; o >>= 1) s += __shfl_down_sync(0xffffffffu, s, o);
        if (lane == 0) g_G[role][p] = s;
    }
    __syncthreads();

    // Phase 3: loss + Adam
    if (threadIdx.x == 0) {
        double t1 = log(S1) - logN;              // lse(f1) - logN
        double t2 = 0.5 * (log(S2) - logN);      // (lse(f2) - logN)/ALPHA
        g_losses[step] = (float)(t1 - t2);
    }
    if (threadIdx.x < 73) {
        int t = threadIdx.x;
        float g = (float)(g_G[1][t] / S2 - g_G[0][t] / S1);
        float m = 0.9f   * g_m[t] + 0.1f   * g;
        float v = 0.999f * g_v[t] + 0.001f * g * g;
        g_m[t] = m; g_v[t] = v;
        g_P[t] -= 1e-3f * (m / bc1) / (sqrtf(v / bc2) + 1e-8f);
    }
}

// ============================================================================
// Output: reference returns (losses[-1], losses) -> 9 floats (or 8 / 1)
// ============================================================================
__global__ void rmi_write_out(float* __restrict__ out, int out_size) {
    for (int i = threadIdx.x; i < out_size; i += blockDim.x) {
        float v;
        if (out_size == NSTEPS)      v = g_losses[i];
        else if (out_size == 1)      v = g_losses[NSTEPS - 1];
        else {
            if (i == 0)              v = g_losses[NSTEPS - 1];
            else if (i <= NSTEPS)    v = g_losses[i - 1];
            else                     v = 0.f;
        }
        out[i] = v;
    }
}

// ============================================================================
// Host driver (graph-capturable: kernel launches + CUB sorts only)
// ============================================================================
extern "C" void kernel_launch(void* const* d_in, const int* in_sizes, int n_in,
                              void* d_out, int out_size) {
    const float* x  = (const float*)d_in[0];
    const float* y  = (const float*)d_in[1];
    const float* w1 = (const float*)d_in[2];
    const float* b1 = (const float*)d_in[3];
    const float* w2 = (const float*)d_in[4];
    const float* b2 = (const float*)d_in[5];
    int N = in_sizes[0] / 8;
    if (N > MAXN) N = MAXN;

    rmi_init_params<<<1, 128>>>(w1, b1, w2, b2);

    // --- shuffle subkeys (host, input-independent, deterministic) ---
    // master key(42) = (0,42); fold-like split: key_s = tf(master,(0,s));
    // per round: new_key = tf(K,(0,0)), subkey = tf(K,(0,1)).
    int rounds = (int)ceil(3.0 * log((double)N) / (32.0 * log(2.0)));
    if (rounds < 1) rounds = 1;
    if (rounds > 4) rounds = 4;

    SubKeys subk[4];
    for (int s = 0; s < NSTEPS; s++) {
        unsigned K0, K1;
        tf2x32(0u, 42u, 0u, (unsigned)s, K0, K1);
        for (int r = 0; r < rounds; r++) {
            unsigned nk0, nk1, sb0, sb1;
            tf2x32(K0, K1, 0u, 0u, nk0, nk1);
            tf2x32(K0, K1, 0u, 1u, sb0, sb1);
            subk[r].k0[s] = sb0; subk[r].k1[s] = sb1;
            K0 = nk0; K1 = nk1;
        }
    }

    unsigned long long *kA, *kB; unsigned *vA, *vB; void* tmp;
    cudaGetSymbolAddress((void**)&kA, g_keysA);
    cudaGetSymbolAddress((void**)&kB, g_keysB);
    cudaGetSymbolAddress((void**)&vA, g_valsA);
    cudaGetSymbolAddress((void**)&vB, g_valsB);
    cudaGetSymbolAddress(&tmp, g_cubtmp);

    // One batched stable radix sort per shuffle round: 8M pairs, bits [0,35).
    // Stable LSD radix == jax lax.sort_key_val stability; the high 3 bits keep
    // the 8 permutation segments separate within a single full-occupancy sort.
    int total = NSTEPS * N;
    unsigned *vcur = vA, *valt = vB;
    for (int r = 0; r < rounds; r++) {
        rmi_gen_keys<<<4096, 256>>>(subk[r], N, kA,
                                    r == 0 ? vcur : (unsigned*)nullptr);
        cub::DoubleBuffer<unsigned long long> dk(kA, kB);
        cub::DoubleBuffer<unsigned>           dv(vcur, valt);
        size_t bytes = sizeof(g_cubtmp);
        cub::DeviceRadixSort::SortPairs(tmp, bytes, dk, dv, total, 0, 35);
        if (dv.selector == 1) { unsigned* t = vcur; vcur = valt; valt = t; }
    }
    const unsigned* perms = vcur;

    // --- 8 fused training steps ---
    const double logN = log((double)N);
    for (int s = 0; s < NSTEPS; s++) {
        const unsigned* pi = perms + (size_t)s * N;
        rmi_fused_step<<<2 * HALFB, GNT>>>(x, y, pi, N);
        double t = (double)(s + 1);
        float bc1 = (float)(1.0 - pow(0.9,   t));
        float bc2 = (float)(1.0 - pow(0.999, t));
        rmi_finalize<<<1, 1024>>>(s, bc1, bc2, logN);
    }

    rmi_write_out<<<1, 32>>>((float*)d_out, out_size);
}

// round 6
// speedup vs baseline: 1.1895x; 1.0241x over previous
#include <cuda_runtime.h>
#include <cstdint>
#include <math.h>
#include <cub/cub.cuh>

// ============================================================================
// Problem constants
// ============================================================================
#define MAXN    1048576
#define NSTEPS  8
#define HALFB   1024      // blocks per role; total grid = 2*HALFB
#define GNT     128       // threads per block
#define IDXBITS 21        // low bits of sort key carry the element index
#define IDXMASK ((1ull << IDXBITS) - 1ull)

struct SubKeys { unsigned k0[NSTEPS]; unsigned k1[NSTEPS]; };

// ============================================================================
// Static device scratch (no dynamic allocation allowed)
// ============================================================================
__device__ __align__(256) unsigned long long g_keysA[NSTEPS * MAXN];
__device__ __align__(256) unsigned long long g_keysB[NSTEPS * MAXN];
__device__ __align__(256) unsigned           g_perms[NSTEPS * MAXN];
__device__ __align__(256) unsigned char      g_cubtmp[64u << 20];

__device__ float  g_P[73];                    // [0..63]=w1, [64..67]=b1, [68..71]=w2, [72]=b2
__device__ float  g_m[73];
__device__ float  g_v[73];
__device__ float  g_partial[2][73][HALFB];    // unnormalized grad partials per role/param/block
__device__ double g_S[2][HALFB];              // unnormalized softmax sums per role/block
__device__ double g_G[2][73];
__device__ float  g_losses[NSTEPS];

// ============================================================================
// Threefry2x32 — exact JAX implementation (20 rounds, 5 key injections)
// ============================================================================
__host__ __device__ __forceinline__ void tf2x32(unsigned k0, unsigned k1,
                                                unsigned c0, unsigned c1,
                                                unsigned &o0, unsigned &o1) {
    unsigned ks0 = k0, ks1 = k1, ks2 = k0 ^ k1 ^ 0x1BD11BDAu;
    unsigned x0 = c0 + ks0, x1 = c1 + ks1;
#define TFR(r) { x0 += x1; x1 = (x1 << (r)) | (x1 >> (32 - (r))); x1 ^= x0; }
    TFR(13) TFR(15) TFR(26) TFR(6)
    x0 += ks1; x1 += ks2 + 1u;
    TFR(17) TFR(29) TFR(16) TFR(24)
    x0 += ks2; x1 += ks0 + 2u;
    TFR(13) TFR(15) TFR(26) TFR(6)
    x0 += ks0; x1 += ks1 + 3u;
    TFR(17) TFR(29) TFR(16) TFR(24)
    x0 += ks1; x1 += ks2 + 4u;
    TFR(13) TFR(15) TFR(26) TFR(6)
    x0 += ks2; x1 += ks0 + 5u;
#undef TFR
    o0 = x0; o1 = x1;
}

// Round-1 keys: (seg << 53) | (random_bits << 21) | idx. Keys-only stable sort
// over bits [21,56) == stable sort_key_val by (segment, bits); the index rides
// in the untouched low bits.
__global__ void rmi_gen_keys1(SubKeys sk, int N, unsigned long long* __restrict__ keys) {
    long long total  = (long long)NSTEPS * N;
    long long stride = (long long)gridDim.x * blockDim.x;
    for (long long idx = (long long)blockIdx.x * blockDim.x + threadIdx.x;
         idx < total; idx += stride) {
        int g = (int)(idx / N);
        unsigned i = (unsigned)(idx - (long long)g * N);
        unsigned a, b;
        tf2x32(sk.k0[g], sk.k1[g], 0u, i, a, b);
        keys[idx] = ((unsigned long long)g << 53)
                  | ((unsigned long long)(a ^ b) << IDXBITS)
                  | (unsigned long long)i;
    }
}

// Round>=2: replace the random-bit field in place; the carried index (low bits)
// is the value being permuted. New bits are indexed by current POSITION within
// the segment, matching jax (each shuffle round draws bits for positions).
__global__ void rmi_regen_keys(SubKeys sk, int N, unsigned long long* __restrict__ keys) {
    long long total  = (long long)NSTEPS * N;
    long long stride = (long long)gridDim.x * blockDim.x;
    for (long long idx = (long long)blockIdx.x * blockDim.x + threadIdx.x;
         idx < total; idx += stride) {
        int g = (int)(idx / N);
        unsigned pos = (unsigned)(idx - (long long)g * N);
        unsigned a, b;
        tf2x32(sk.k0[g], sk.k1[g], 0u, pos, a, b);
        unsigned long long k = keys[idx];
        keys[idx] = ((unsigned long long)g << 53)
                  | ((unsigned long long)(a ^ b) << IDXBITS)
                  | (k & IDXMASK);
    }
}

__global__ void rmi_extract(int N, const unsigned long long* __restrict__ keys,
                            unsigned* __restrict__ vals) {
    long long total  = (long long)NSTEPS * N;
    long long stride = (long long)gridDim.x * blockDim.x;
    for (long long idx = (long long)blockIdx.x * blockDim.x + threadIdx.x;
         idx < total; idx += stride)
        vals[idx] = (unsigned)(keys[idx] & IDXMASK);
}

// ============================================================================
// Parameter init
// ============================================================================
__global__ void rmi_init_params(const float* __restrict__ w1,
                                const float* __restrict__ b1,
                                const float* __restrict__ w2,
                                const float* __restrict__ b2) {
    int t = threadIdx.x;
    if (t < 64)       g_P[t] = w1[t];
    else if (t < 68)  g_P[t] = b1[t - 64];
    else if (t < 72)  g_P[t] = w2[t - 68];
    else if (t == 72) g_P[72] = b2[0];
    if (t < 73) { g_m[t] = 0.f; g_v[t] = 0.f; }
}

// ============================================================================
// Tiny-MLP helpers (all register-resident)
// ============================================================================
__device__ __forceinline__ void load8(const float* __restrict__ base, unsigned row,
                                      float* __restrict__ dst) {
    const float4* p = (const float4*)base + 2ull * row;
    float4 a = __ldg(p), b = __ldg(p + 1);
    dst[0] = a.x; dst[1] = a.y; dst[2] = a.z; dst[3] = a.w;
    dst[4] = b.x; dst[5] = b.y; dst[6] = b.z; dst[7] = b.w;
}

// tanh via exp: abs err ~1e-7, MUFU-cheap. Consumers are 1M-sample sums, so
// absolute (not relative) error is what propagates.
__device__ __forceinline__ float ftanh(float x) {
    float e = __expf(2.f * x);
    return 1.f - 2.f * __frcp_rn(e + 1.f);
}

// ============================================================================
// Fused per-step pass: role 0 -> (S1, G1) over (x_i, y_i);
//                      role 1 -> (S2, G2) over (x_i, y_{pi_i}) with f2 = 2*o.
// Weights and accumulators in registers (launch_bounds(128,2) -> ~195 regs,
// no spills). Software pipeline: pi fetched 2 iterations ahead, x/y 1 ahead.
// ============================================================================
__global__ void __launch_bounds__(GNT, 2)
rmi_fused_step(const float* __restrict__ x, const float* __restrict__ y,
               const unsigned* __restrict__ pi, int N) {
    const int role = blockIdx.x & 1;
    const int b    = blockIdx.x >> 1;
    const int stride = HALFB * GNT;

    float P[73];
#pragma unroll
    for (int t = 0; t < 73; t++) P[t] = g_P[t];

    float acc[73];
#pragma unroll
    for (int t = 0; t < 73; t++) acc[t] = 0.f;
    float S = 0.f;

    int i = b * GNT + threadIdx.x;
    float cur[16], nxt[16];
    unsigned rown = 0;
    if (i < N) {
        unsigned r0 = role ? __ldg(pi + i) : (unsigned)i;
        load8(x, (unsigned)i, cur);
        load8(y, r0, cur + 8);
        int i1 = i + stride;
        if (i1 < N) rown = role ? __ldg(pi + i1) : (unsigned)i1;
    }

    for (; i < N; i += stride) {
        const int inx = i + stride;
        // ---- prefetch next sample (row index already resolved) ----
        if (inx < N) {
            load8(x, (unsigned)inx, nxt);
            load8(y, rown, nxt + 8);
        }
        const int inx2 = inx + stride;
        unsigned rown2 = 0;
        if (inx2 < N) rown2 = role ? __ldg(pi + inx2) : (unsigned)inx2;

        // ---- forward ----
        float h[4];
        float s = P[72];
#pragma unroll
        for (int k = 0; k < 4; k++) {
            float u = P[64 + k];
#pragma unroll
            for (int j = 0; j < 16; j++) u = fmaf(P[k * 16 + j], cur[j], u);
            float hk = ftanh(u);
            h[k] = hk;
            s = fmaf(P[68 + k], hk, s);
        }
        float o = ftanh(s);
        float f = role ? 2.f * o : o;       // ALPHA=2: f2 = 2*est, f1 = est
        float w = __expf(f);                // no shift needed: |f| <= 2
        S += w;

        // ---- backward (weighted by unnormalized softmax w) ----
        float d = w * (1.f - o * o);
        acc[72] += d;
#pragma unroll
        for (int k = 0; k < 4; k++) {
            acc[68 + k] = fmaf(d, h[k], acc[68 + k]);
            float e = d * P[68 + k] * (1.f - h[k] * h[k]);
            acc[64 + k] += e;
#pragma unroll
            for (int j = 0; j < 16; j++)
                acc[k * 16 + j] = fmaf(e, cur[j], acc[k * 16 + j]);
        }

        // ---- rotate pipeline ----
        if (inx < N) {
#pragma unroll
            for (int j = 0; j < 16; j++) cur[j] = nxt[j];
        }
        rown = rown2;
    }

    // --- deterministic block reduction of 73 accumulators ---
#pragma unroll
    for (int t = 0; t < 73; t++) {
        float v = acc[t];
#pragma unroll
        for (int o = 16; o > 0; o >>= 1) v += __shfl_down_sync(0xffffffffu, v, o);
        acc[t] = v;
    }
    __shared__ float wsum[GNT / 32][73];
    int wid = threadIdx.x >> 5, lane = threadIdx.x & 31;
    if (lane == 0) {
#pragma unroll
        for (int t = 0; t < 73; t++) wsum[wid][t] = acc[t];
    }
    __syncthreads();
    if (threadIdx.x < 73) {
        float s = 0.f;
#pragma unroll
        for (int w = 0; w < GNT / 32; w++) s += wsum[w][threadIdx.x];
        g_partial[role][threadIdx.x][b] = s;
    }

    // --- deterministic block reduction of S (fp64 tree) ---
    __shared__ double red[GNT];
    red[threadIdx.x] = (double)S;
    __syncthreads();
    for (int o = GNT / 2; o > 0; o >>= 1) {
        if (threadIdx.x < (unsigned)o) red[threadIdx.x] += red[threadIdx.x + o];
        __syncthreads();
    }
    if (threadIdx.x == 0) g_S[role][b] = red[0];
}

// ============================================================================
// Finalize: S totals, loss, grad normalization, Adam. One block, 1024 threads.
// All reductions fixed-shape -> bit-deterministic across replays.
// ============================================================================
__global__ void __launch_bounds__(1024)
rmi_finalize(int step, float bc1, float bc2, double logN) {
    __shared__ double red[256];
    __shared__ double sS[2];

    if (threadIdx.x < 256) {
        int role = threadIdx.x >> 7;
        int lane = threadIdx.x & 127;
        double s = 0.0;
        for (int bb = lane; bb < HALFB; bb += 128) s += g_S[role][bb];
        red[threadIdx.x] = s;
    }
    __syncthreads();
    for (int o = 64; o > 0; o >>= 1) {
        if (threadIdx.x < 256 && (threadIdx.x & 127) < o)
            red[threadIdx.x] += red[threadIdx.x + o];
        __syncthreads();
    }
    if (threadIdx.x == 0)   sS[0] = red[0];
    if (threadIdx.x == 128) sS[1] = red[128];
    __syncthreads();
    double S1 = sS[0], S2 = sS[1];

    int wid = threadIdx.x >> 5, lane = threadIdx.x & 31;
    for (int row = wid; row < 146; row += 32) {
        int role = row >= 73 ? 1 : 0;
        int p = role ? row - 73 : row;
        const float* src = &g_partial[role][p][0];
        double s = 0.0;
        for (int bb = lane; bb < HALFB; bb += 32) s += (double)__ldg(src + bb);
#pragma unroll
        for (int o = 16; o > 0; o >>= 1) s += __shfl_down_sync(0xffffffffu, s, o);
        if (lane == 0) g_G[role][p] = s;
    }
    __syncthreads();

    if (threadIdx.x == 0) {
        double t1 = log(S1) - logN;              // lse(f1) - logN
        double t2 = 0.5 * (log(S2) - logN);      // (lse(f2) - logN)/ALPHA
        g_losses[step] = (float)(t1 - t2);
    }
    if (threadIdx.x < 73) {
        int t = threadIdx.x;
        float g = (float)(g_G[1][t] / S2 - g_G[0][t] / S1);
        float m = 0.9f   * g_m[t] + 0.1f   * g;
        float v = 0.999f * g_v[t] + 0.001f * g * g;
        g_m[t] = m; g_v[t] = v;
        g_P[t] -= 1e-3f * (m / bc1) / (sqrtf(v / bc2) + 1e-8f);
    }
}

// ============================================================================
// Output: reference returns (losses[-1], losses) -> 9 floats (or 8 / 1)
// ============================================================================
__global__ void rmi_write_out(float* __restrict__ out, int out_size) {
    for (int i = threadIdx.x; i < out_size; i += blockDim.x) {
        float v;
        if (out_size == NSTEPS)      v = g_losses[i];
        else if (out_size == 1)      v = g_losses[NSTEPS - 1];
        else {
            if (i == 0)              v = g_losses[NSTEPS - 1];
            else if (i <= NSTEPS)    v = g_losses[i - 1];
            else                     v = 0.f;
        }
        out[i] = v;
    }
}

// ============================================================================
// Host driver (graph-capturable: kernel launches + CUB sorts only)
// ============================================================================
extern "C" void kernel_launch(void* const* d_in, const int* in_sizes, int n_in,
                              void* d_out, int out_size) {
    const float* x  = (const float*)d_in[0];
    const float* y  = (const float*)d_in[1];
    const float* w1 = (const float*)d_in[2];
    const float* b1 = (const float*)d_in[3];
    const float* w2 = (const float*)d_in[4];
    const float* b2 = (const float*)d_in[5];
    int N = in_sizes[0] / 8;
    if (N > MAXN) N = MAXN;

    rmi_init_params<<<1, 128>>>(w1, b1, w2, b2);

    // --- shuffle subkeys (host, input-independent, deterministic) ---
    // master key(42) = (0,42); fold-like split: key_s = tf(master,(0,s));
    // per round: new_key = tf(K,(0,0)), subkey = tf(K,(0,1)).
    int rounds = (int)ceil(3.0 * log((double)N) / (32.0 * log(2.0)));
    if (rounds < 1) rounds = 1;
    if (rounds > 4) rounds = 4;

    SubKeys subk[4];
    for (int s = 0; s < NSTEPS; s++) {
        unsigned K0, K1;
        tf2x32(0u, 42u, 0u, (unsigned)s, K0, K1);
        for (int r = 0; r < rounds; r++) {
            unsigned nk0, nk1, sb0, sb1;
            tf2x32(K0, K1, 0u, 0u, nk0, nk1);
            tf2x32(K0, K1, 0u, 1u, sb0, sb1);
            subk[r].k0[s] = sb0; subk[r].k1[s] = sb1;
            K0 = nk0; K1 = nk1;
        }
    }

    unsigned long long *kA, *kB; unsigned *pv; void* tmp;
    cudaGetSymbolAddress((void**)&kA, g_keysA);
    cudaGetSymbolAddress((void**)&kB, g_keysB);
    cudaGetSymbolAddress((void**)&pv, g_perms);
    cudaGetSymbolAddress(&tmp, g_cubtmp);

    // Keys-only batched stable radix sorts: bits [21, 56) = (seg, random bits);
    // low 21 bits carry the permuted index as payload.
    int total = NSTEPS * N;
    cub::DoubleBuffer<unsigned long long> dk(kA, kB);
    for (int r = 0; r < rounds; r++) {
        if (r == 0) rmi_gen_keys1<<<4096, 256>>>(subk[r], N, dk.Current());
        else        rmi_regen_keys<<<4096, 256>>>(subk[r], N, dk.Current());
        size_t bytes = sizeof(g_cubtmp);
        cub::DeviceRadixSort::SortKeys(tmp, bytes, dk, total, IDXBITS, 56);
    }
    rmi_extract<<<2048, 256>>>(N, dk.Current(), pv);

    // --- 8 fused training steps ---
    const double logN = log((double)N);
    for (int s = 0; s < NSTEPS; s++) {
        const unsigned* pi = pv + (size_t)s * N;
        rmi_fused_step<<<2 * HALFB, GNT>>>(x, y, pi, N);
        double t = (double)(s + 1);
        float bc1 = (float)(1.0 - pow(0.9,   t));
        float bc2 = (float)(1.0 - pow(0.999, t));
        rmi_finalize<<<1, 1024>>>(s, bc1, bc2, logN);
    }

    rmi_write_out<<<1, 32>>>((float*)d_out, out_size);
}

// round 8
// speedup vs baseline: 1.3065x; 1.0984x over previous
#include <cuda_runtime.h>
#include <cstdint>
#include <math.h>
#include <cub/block/block_radix_sort.cuh>

// ============================================================================
// Problem constants
// ============================================================================
#define MAXN    1048576
#define NSTEPS  8
#define NSEG    8               // 8 permutations (one per training step)
#define HALFB   1024            // blocks per role in step kernel
#define GNT     128             // threads per block in step kernel

// --- custom permutation sort configuration ---
#define BBITS   11              // MSD bucket bits
#define NBKT    (1 << BBITS)    // 2048 buckets per segment
#define LOWBITS (32 - BBITS)    // 21 low key bits
#define LOWMASK ((1u << LOWBITS) - 1u)
#define POSBITS 21              // position field in payload (N < 2^21)
#define POSMASK ((1u << POSBITS) - 1u)
#define CAP     896             // bucket capacity (avg ~490, +18 sigma)
#define SORT_T  128
#define SORT_I  7               // 128*7 = 896 = CAP
#define SCAT_T  512
#define SCAT_I  16
#define CHUNK   (SCAT_T * SCAT_I)   // 8192 elements per scatter CTA

struct SubKeys { unsigned k0[NSEG]; unsigned k1[NSEG]; };

// ============================================================================
// Static device scratch (no dynamic allocation allowed)
// ============================================================================
__device__ __align__(256) unsigned long long g_pay[NSEG * MAXN];   // bucketed payloads
__device__ __align__(256) unsigned           g_v1[NSEG * MAXN];    // round-1 result
__device__ __align__(256) unsigned           g_perms[NSEG * MAXN]; // final permutations
__device__ unsigned g_hist[2][NSEG * NBKT];
__device__ unsigned g_base[2][NSEG * NBKT];
__device__ unsigned g_cursor[2][NSEG * NBKT];

__device__ float  g_P[73];                    // [0..63]=w1, [64..67]=b1, [68..71]=w2, [72]=b2
__device__ float  g_m[73];
__device__ float  g_v[73];
__device__ float  g_partial[2][73][HALFB];
__device__ double g_S[2][HALFB];
__device__ double g_G[2][73];
__device__ float  g_losses[NSTEPS];

// ============================================================================
// Threefry2x32 — exact JAX implementation (20 rounds, 5 key injections)
// ============================================================================
__host__ __device__ __forceinline__ void tf2x32(unsigned k0, unsigned k1,
                                                unsigned c0, unsigned c1,
                                                unsigned &o0, unsigned &o1) {
    unsigned ks0 = k0, ks1 = k1, ks2 = k0 ^ k1 ^ 0x1BD11BDAu;
    unsigned x0 = c0 + ks0, x1 = c1 + ks1;
#define TFR(r) { x0 += x1; x1 = (x1 << (r)) | (x1 >> (32 - (r))); x1 ^= x0; }
    TFR(13) TFR(15) TFR(26) TFR(6)
    x0 += ks1; x1 += ks2 + 1u;
    TFR(17) TFR(29) TFR(16) TFR(24)
    x0 += ks2; x1 += ks0 + 2u;
    TFR(13) TFR(15) TFR(26) TFR(6)
    x0 += ks0; x1 += ks1 + 3u;
    TFR(17) TFR(29) TFR(16) TFR(24)
    x0 += ks1; x1 += ks2 + 4u;
    TFR(13) TFR(15) TFR(26) TFR(6)
    x0 += ks2; x1 += ks0 + 5u;
#undef TFR
    o0 = x0; o1 = x1;
}

__device__ __forceinline__ unsigned rnd_bits(const SubKeys& sk, int s, unsigned p) {
    unsigned a, b;
    tf2x32(sk.k0[s], sk.k1[s], 0u, p, a, b);
    return a ^ b;   // partitionable-threefry 32-bit random_bits
}

// ============================================================================
// Permutation pipeline.
// jax.random.permutation = 2 rounds of stable sort_key_val by uniform 32-bit
// keys. Stable order == total order by (key32, position). We MSD-bucket by the
// top 11 key bits (histogram+scan+scatter), then sort each ~490-element bucket
// in shared memory by the remaining (low21, pos21) 42-bit payload — unique per
// element, so any scatter order is corrected exactly.
// ============================================================================
__global__ void rmi_zero_hist() {
    int i = blockIdx.x * blockDim.x + threadIdx.x;
    if (i < NSEG * NBKT) { g_hist[0][i] = 0; g_hist[1][i] = 0; }
}

__global__ void __launch_bounds__(SCAT_T)
rmi_hist(SubKeys sk1, SubKeys sk2, int N, int cps) {
    int s = blockIdx.x / cps, c = blockIdx.x % cps;
    __shared__ unsigned h1[NBKT], h2[NBKT];
    for (int b = threadIdx.x; b < NBKT; b += SCAT_T) { h1[b] = 0; h2[b] = 0; }
    __syncthreads();
    int p0 = c * CHUNK;
#pragma unroll
    for (int j = 0; j < SCAT_I; j++) {
        int p = p0 + j * SCAT_T + threadIdx.x;
        if (p < N) {
            atomicAdd(&h1[rnd_bits(sk1, s, (unsigned)p) >> LOWBITS], 1u);
            atomicAdd(&h2[rnd_bits(sk2, s, (unsigned)p) >> LOWBITS], 1u);
        }
    }
    __syncthreads();
    for (int b = threadIdx.x; b < NBKT; b += SCAT_T) {
        if (h1[b]) atomicAdd(&g_hist[0][s * NBKT + b], h1[b]);
        if (h2[b]) atomicAdd(&g_hist[1][s * NBKT + b], h2[b]);
    }
}

// 16 warps: one per (round, segment); sequential exclusive scan over 2048
// buckets; bases are absolute (include s*N).
__global__ void __launch_bounds__(512) rmi_scan(int N) {
    int w = threadIdx.x >> 5, lane = threadIdx.x & 31;
    if (w >= 16) return;
    int r = w >> 3, s = w & 7;
    const unsigned* h = &g_hist[r][s * NBKT];
    unsigned* bs = &g_base[r][s * NBKT];
    unsigned* cu = &g_cursor[r][s * NBKT];
    unsigned carry = 0;
    for (int c0 = 0; c0 < NBKT; c0 += 32) {
        unsigned v = h[c0 + lane], orig = v;
#pragma unroll
        for (int o = 1; o < 32; o <<= 1) {
            unsigned t = __shfl_up_sync(0xffffffffu, v, o);
            if (lane >= o) v += t;
        }
        unsigned excl = carry + v - orig + (unsigned)(s * N);
        bs[c0 + lane] = excl;
        cu[c0 + lane] = excl;
        carry += __shfl_sync(0xffffffffu, v, 31);
    }
}

__global__ void __launch_bounds__(SCAT_T)
rmi_scatter(SubKeys sk, int N, int cps, int round) {
    int s = blockIdx.x / cps, c = blockIdx.x % cps;
    __shared__ unsigned cnt[NBKT];
    for (int b = threadIdx.x; b < NBKT; b += SCAT_T) cnt[b] = 0;
    __syncthreads();
    int p0 = c * CHUNK;
    unsigned bits[SCAT_I];
#pragma unroll
    for (int j = 0; j < SCAT_I; j++) {
        int p = p0 + j * SCAT_T + threadIdx.x;
        unsigned bb = 0;
        if (p < N) {
            bb = rnd_bits(sk, s, (unsigned)p);
            atomicAdd(&cnt[bb >> LOWBITS], 1u);
        }
        bits[j] = bb;
    }
    __syncthreads();
    unsigned* cursor = &g_cursor[round][s * NBKT];
    for (int b = threadIdx.x; b < NBKT; b += SCAT_T) {
        unsigned cc = cnt[b];
        cnt[b] = cc ? atomicAdd(&cursor[b], cc) : 0u;   // absolute base for this CTA
    }
    __syncthreads();
#pragma unroll
    for (int j = 0; j < SCAT_I; j++) {
        int p = p0 + j * SCAT_T + threadIdx.x;
        if (p < N) {
            unsigned bb = bits[j];
            unsigned slot = atomicAdd(&cnt[bb >> LOWBITS], 1u);
            g_pay[slot] = ((unsigned long long)(bb & LOWMASK) << POSBITS)
                        | (unsigned long long)(unsigned)p;
        }
    }
}

// One CTA per (segment, bucket): sort <=896 payloads by 42 unique bits, write
// permuted values. Round 0 value = pos; round 1 value = v1[pos] (gather).
template <int ROUND>
__global__ void __launch_bounds__(SORT_T)
rmi_bucket_sort(int N, unsigned* __restrict__ out) {
    int s = blockIdx.x >> BBITS, b = blockIdx.x & (NBKT - 1);
    unsigned n = g_hist[ROUND][s * NBKT + b];
    if (n > CAP) n = CAP;                      // P(overflow) ~ 1e-25
    unsigned base = g_base[ROUND][s * NBKT + b];   // absolute

    typedef cub::BlockRadixSort<unsigned long long, SORT_T, SORT_I> Sorter;
    __shared__ typename Sorter::TempStorage ts;

    unsigned long long keys[SORT_I];
#pragma unroll
    for (int k = 0; k < SORT_I; k++) {
        unsigned r = threadIdx.x * SORT_I + k;
        keys[k] = (r < n) ? g_pay[base + r] : ~0ull;
    }
    Sorter(ts).Sort(keys, 0, LOWBITS + POSBITS);
#pragma unroll
    for (int k = 0; k < SORT_I; k++) {
        unsigned r = threadIdx.x * SORT_I + k;
        if (r < n) {
            unsigned pos = (unsigned)keys[k] & POSMASK;
            unsigned val = (ROUND == 0) ? pos : __ldg(&g_v1[s * N + pos]);
            out[base + r] = val;
        }
    }
}

// ============================================================================
// Parameter init
// ============================================================================
__global__ void rmi_init_params(const float* __restrict__ w1,
                                const float* __restrict__ b1,
                                const float* __restrict__ w2,
                                const float* __restrict__ b2) {
    int t = threadIdx.x;
    if (t < 64)       g_P[t] = w1[t];
    else if (t < 68)  g_P[t] = b1[t - 64];
    else if (t < 72)  g_P[t] = w2[t - 68];
    else if (t == 72) g_P[72] = b2[0];
    if (t < 73) { g_m[t] = 0.f; g_v[t] = 0.f; }
}

// ============================================================================
// Tiny-MLP helpers (all register-resident)
// ============================================================================
__device__ __forceinline__ void load8(const float* __restrict__ base, unsigned row,
                                      float* __restrict__ dst) {
    const float4* p = (const float4*)base + 2ull * row;
    float4 a = __ldg(p), b = __ldg(p + 1);
    dst[0] = a.x; dst[1] = a.y; dst[2] = a.z; dst[3] = a.w;
    dst[4] = b.x; dst[5] = b.y; dst[6] = b.z; dst[7] = b.w;
}

__device__ __forceinline__ float ftanh(float x) {
    float e = __expf(2.f * x);
    return 1.f - 2.f * __frcp_rn(e + 1.f);
}

// ============================================================================
// Fused per-step pass (unchanged from the passing R6 kernel)
// ============================================================================
__global__ void __launch_bounds__(GNT, 2)
rmi_fused_step(const float* __restrict__ x, const float* __restrict__ y,
               const unsigned* __restrict__ pi, int N) {
    const int role = blockIdx.x & 1;
    const int b    = blockIdx.x >> 1;
    const int stride = HALFB * GNT;

    float P[73];
#pragma unroll
    for (int t = 0; t < 73; t++) P[t] = g_P[t];

    float acc[73];
#pragma unroll
    for (int t = 0; t < 73; t++) acc[t] = 0.f;
    float S = 0.f;

    int i = b * GNT + threadIdx.x;
    float cur[16], nxt[16];
    unsigned rown = 0;
    if (i < N) {
        unsigned r0 = role ? __ldg(pi + i) : (unsigned)i;
        load8(x, (unsigned)i, cur);
        load8(y, r0, cur + 8);
        int i1 = i + stride;
        if (i1 < N) rown = role ? __ldg(pi + i1) : (unsigned)i1;
    }

    for (; i < N; i += stride) {
        const int inx = i + stride;
        if (inx < N) {
            load8(x, (unsigned)inx, nxt);
            load8(y, rown, nxt + 8);
        }
        const int inx2 = inx + stride;
        unsigned rown2 = 0;
        if (inx2 < N) rown2 = role ? __ldg(pi + inx2) : (unsigned)inx2;

        float h[4];
        float s = P[72];
#pragma unroll
        for (int k = 0; k < 4; k++) {
            float u = P[64 + k];
#pragma unroll
            for (int j = 0; j < 16; j++) u = fmaf(P[k * 16 + j], cur[j], u);
            float hk = ftanh(u);
            h[k] = hk;
            s = fmaf(P[68 + k], hk, s);
        }
        float o = ftanh(s);
        float f = role ? 2.f * o : o;
        float w = __expf(f);
        S += w;

        float d = w * (1.f - o * o);
        acc[72] += d;
#pragma unroll
        for (int k = 0; k < 4; k++) {
            acc[68 + k] = fmaf(d, h[k], acc[68 + k]);
            float e = d * P[68 + k] * (1.f - h[k] * h[k]);
            acc[64 + k] += e;
#pragma unroll
            for (int j = 0; j < 16; j++)
                acc[k * 16 + j] = fmaf(e, cur[j], acc[k * 16 + j]);
        }

        if (inx < N) {
#pragma unroll
            for (int j = 0; j < 16; j++) cur[j] = nxt[j];
        }
        rown = rown2;
    }

#pragma unroll
    for (int t = 0; t < 73; t++) {
        float v = acc[t];
#pragma unroll
        for (int o = 16; o > 0; o >>= 1) v += __shfl_down_sync(0xffffffffu, v, o);
        acc[t] = v;
    }
    __shared__ float wsum[GNT / 32][73];
    int wid = threadIdx.x >> 5, lane = threadIdx.x & 31;
    if (lane == 0) {
#pragma unroll
        for (int t = 0; t < 73; t++) wsum[wid][t] = acc[t];
    }
    __syncthreads();
    if (threadIdx.x < 73) {
        float s = 0.f;
#pragma unroll
        for (int w = 0; w < GNT / 32; w++) s += wsum[w][threadIdx.x];
        g_partial[role][threadIdx.x][b] = s;
    }

    __shared__ double red[GNT];
    red[threadIdx.x] = (double)S;
    __syncthreads();
    for (int o = GNT / 2; o > 0; o >>= 1) {
        if (threadIdx.x < (unsigned)o) red[threadIdx.x] += red[threadIdx.x + o];
        __syncthreads();
    }
    if (threadIdx.x == 0) g_S[role][b] = red[0];
}

// ============================================================================
// Finalize (unchanged from R6)
// ============================================================================
__global__ void __launch_bounds__(1024)
rmi_finalize(int step, float bc1, float bc2, double logN) {
    __shared__ double red[256];
    __shared__ double sS[2];

    if (threadIdx.x < 256) {
        int role = threadIdx.x >> 7;
        int lane = threadIdx.x & 127;
        double s = 0.0;
        for (int bb = lane; bb < HALFB; bb += 128) s += g_S[role][bb];
        red[threadIdx.x] = s;
    }
    __syncthreads();
    for (int o = 64; o > 0; o >>= 1) {
        if (threadIdx.x < 256 && (threadIdx.x & 127) < o)
            red[threadIdx.x] += red[threadIdx.x + o];
        __syncthreads();
    }
    if (threadIdx.x == 0)   sS[0] = red[0];
    if (threadIdx.x == 128) sS[1] = red[128];
    __syncthreads();
    double S1 = sS[0], S2 = sS[1];

    int wid = threadIdx.x >> 5, lane = threadIdx.x & 31;
    for (int row = wid; row < 146; row += 32) {
        int role = row >= 73 ? 1 : 0;
        int p = role ? row - 73 : row;
        const float* src = &g_partial[role][p][0];
        double s = 0.0;
        for (int bb = lane; bb < HALFB; bb += 32) s += (double)__ldg(src + bb);
#pragma unroll
        for (int o = 16; o > 0; o >>= 1) s += __shfl_down_sync(0xffffffffu, s, o);
        if (lane == 0) g_G[role][p] = s;
    }
    __syncthreads();

    if (threadIdx.x == 0) {
        double t1 = log(S1) - logN;
        double t2 = 0.5 * (log(S2) - logN);
        g_losses[step] = (float)(t1 - t2);
    }
    if (threadIdx.x < 73) {
        int t = threadIdx.x;
        float g = (float)(g_G[1][t] / S2 - g_G[0][t] / S1);
        float m = 0.9f   * g_m[t] + 0.1f   * g;
        float v = 0.999f * g_v[t] + 0.001f * g * g;
        g_m[t] = m; g_v[t] = v;
        g_P[t] -= 1e-3f * (m / bc1) / (sqrtf(v / bc2) + 1e-8f);
    }
}

__global__ void rmi_write_out(float* __restrict__ out, int out_size) {
    for (int i = threadIdx.x; i < out_size; i += blockDim.x) {
        float v;
        if (out_size == NSTEPS)      v = g_losses[i];
        else if (out_size == 1)      v = g_losses[NSTEPS - 1];
        else {
            if (i == 0)              v = g_losses[NSTEPS - 1];
            else if (i <= NSTEPS)    v = g_losses[i - 1];
            else                     v = 0.f;
        }
        out[i] = v;
    }
}

// ============================================================================
// Host driver (graph-capturable: plain kernel launches only)
// ============================================================================
extern "C" void kernel_launch(void* const* d_in, const int* in_sizes, int n_in,
                              void* d_out, int out_size) {
    const float* x  = (const float*)d_in[0];
    const float* y  = (const float*)d_in[1];
    const float* w1 = (const float*)d_in[2];
    const float* b1 = (const float*)d_in[3];
    const float* w2 = (const float*)d_in[4];
    const float* b2 = (const float*)d_in[5];
    int N = in_sizes[0] / 8;
    if (N > MAXN) N = MAXN;

    rmi_init_params<<<1, 128>>>(w1, b1, w2, b2);

    // --- shuffle subkeys (host, input-independent, deterministic) ---
    // master key(42) = (0,42); fold-like split: key_s = tf(master,(0,s));
    // per round: new_key = tf(K,(0,0)), subkey = tf(K,(0,1)). 2 rounds for
    // N in [1626, 2.6M] (ceil(3*log(N)/log(2^32))).
    SubKeys subk[2];
    for (int s = 0; s < NSEG; s++) {
        unsigned K0, K1;
        tf2x32(0u, 42u, 0u, (unsigned)s, K0, K1);
        for (int r = 0; r < 2; r++) {
            unsigned nk0, nk1, sb0, sb1;
            tf2x32(K0, K1, 0u, 0u, nk0, nk1);
            tf2x32(K0, K1, 0u, 1u, sb0, sb1);
            subk[r].k0[s] = sb0; subk[r].k1[s] = sb1;
            K0 = nk0; K1 = nk1;
        }
    }

    unsigned *v1p, *pp;
    cudaGetSymbolAddress((void**)&v1p, g_v1);
    cudaGetSymbolAddress((void**)&pp, g_perms);

    // --- custom permutation pipeline (2 stable-sort rounds) ---
    const int cps = (N + CHUNK - 1) / CHUNK;
    rmi_zero_hist<<<(NSEG * NBKT + 255) / 256, 256>>>();
    rmi_hist<<<NSEG * cps, SCAT_T>>>(subk[0], subk[1], N, cps);
    rmi_scan<<<1, 512>>>(N);
    rmi_scatter<<<NSEG * cps, SCAT_T>>>(subk[0], N, cps, 0);
    rmi_bucket_sort<0><<<NSEG << BBITS, SORT_T>>>(N, v1p);
    rmi_scatter<<<NSEG * cps, SCAT_T>>>(subk[1], N, cps, 1);
    rmi_bucket_sort<1><<<NSEG << BBITS, SORT_T>>>(N, pp);

    // --- 8 fused training steps ---
    const double logN = log((double)N);
    for (int s = 0; s < NSTEPS; s++) {
        const unsigned* pi = pp + (size_t)s * N;
        rmi_fused_step<<<2 * HALFB, GNT>>>(x, y, pi, N);
        double t = (double)(s + 1);
        float bc1 = (float)(1.0 - pow(0.9,   t));
        float bc2 = (float)(1.0 - pow(0.999, t));
        rmi_finalize<<<1, 1024>>>(s, bc1, bc2, logN);
    }

    rmi_write_out<<<1, 32>>>((float*)d_out, out_size);
}

// round 9
// speedup vs baseline: 1.3196x; 1.0100x over previous
#include <cuda_runtime.h>
#include <cstdint>
#include <math.h>
#include <cub/block/block_radix_sort.cuh>

// ============================================================================
// Problem constants
// ============================================================================
#define MAXN    1048576
#define NSTEPS  8
#define NSEG    8               // 8 permutations (one per training step)
#define HALFB   1024            // blocks per role in step kernel
#define GNT     128             // threads per block in step kernel

// --- permutation sort configuration ---
#define BBITS   11              // MSD bucket bits
#define NBKT    (1 << BBITS)    // 2048 buckets per segment
#define LOWBITS (32 - BBITS)    // 21 low key bits
#define LOWMASK ((1u << LOWBITS) - 1u)
#define POSBITS 21              // position field in payload (N <= 2^20)
#define POSMASK ((1u << POSBITS) - 1u)
#define CAPR    768             // fixed region capacity (avg 512, +11 sigma)
#define SORT_T  128
#define SORT_I  6               // 128*6 = 768 = CAPR
#define CAPF    (SORT_T * SORT_I)
#define SCAT_T  512
#define SCAT_I  16
#define CHUNK   (SCAT_T * SCAT_I)   // 8192 elements per scatter CTA

struct SubKeys { unsigned k0[NSEG]; unsigned k1[NSEG]; };

// ============================================================================
// Static device scratch (no dynamic allocation allowed)
// ============================================================================
__device__ __align__(256) unsigned long long g_pay[NSEG * NBKT * (size_t)CAPR]; // bucket regions
__device__ __align__(256) unsigned           g_v1[NSEG * MAXN];    // round-1 result
__device__ __align__(256) unsigned           g_perms[NSEG * MAXN]; // final permutations
__device__ unsigned g_cursor[2][NSEG * NBKT];   // per-round bucket cursors (= counts)
__device__ unsigned g_base[2][NSEG * NBKT];     // per-round absolute output bases

__device__ float  g_P[73];                    // [0..63]=w1, [64..67]=b1, [68..71]=w2, [72]=b2
__device__ float  g_m[73];
__device__ float  g_v[73];
__device__ float  g_partial[2][73][HALFB];
__device__ double g_S[2][HALFB];
__device__ double g_G[2][73];
__device__ float  g_losses[NSTEPS];

// ============================================================================
// Threefry2x32 — exact JAX implementation (20 rounds, 5 key injections)
// ============================================================================
__host__ __device__ __forceinline__ void tf2x32(unsigned k0, unsigned k1,
                                                unsigned c0, unsigned c1,
                                                unsigned &o0, unsigned &o1) {
    unsigned ks0 = k0, ks1 = k1, ks2 = k0 ^ k1 ^ 0x1BD11BDAu;
    unsigned x0 = c0 + ks0, x1 = c1 + ks1;
#define TFR(r) { x0 += x1; x1 = (x1 << (r)) | (x1 >> (32 - (r))); x1 ^= x0; }
    TFR(13) TFR(15) TFR(26) TFR(6)
    x0 += ks1; x1 += ks2 + 1u;
    TFR(17) TFR(29) TFR(16) TFR(24)
    x0 += ks2; x1 += ks0 + 2u;
    TFR(13) TFR(15) TFR(26) TFR(6)
    x0 += ks0; x1 += ks1 + 3u;
    TFR(17) TFR(29) TFR(16) TFR(24)
    x0 += ks1; x1 += ks2 + 4u;
    TFR(13) TFR(15) TFR(26) TFR(6)
    x0 += ks2; x1 += ks0 + 5u;
#undef TFR
    o0 = x0; o1 = x1;
}

__device__ __forceinline__ unsigned rnd_bits(const SubKeys& sk, int s, unsigned p) {
    unsigned a, b;
    tf2x32(sk.k0[s], sk.k1[s], 0u, p, a, b);
    return a ^ b;   // partitionable-threefry 32-bit random_bits
}

// ============================================================================
// Permutation pipeline: per round (2 rounds, matching jax's 2 stable sorts):
//   scatter -> fixed bucket regions (global atomic slot), payload=(low21,pos)
//   scan    -> exclusive prefix of bucket counts (parallel, per segment)
//   bucket_sort -> stable 21-bit pair sort + pos tie-fix; emit permuted values
// Payload (low21,pos) is unique per element, so atomic slot scrambling is
// fully corrected: output order == jax stable sort by (key32, position).
// ============================================================================
__global__ void rmi_zero_cursors() {
    int i = blockIdx.x * blockDim.x + threadIdx.x;
    if (i < NSEG * NBKT) { g_cursor[0][i] = 0; g_cursor[1][i] = 0; }
}

__global__ void __launch_bounds__(SCAT_T)
rmi_scatter(SubKeys sk, int N, int cps, int round) {
    int s = blockIdx.x / cps, c = blockIdx.x % cps;
    unsigned* cursor = &g_cursor[round][s * NBKT];
    int p0 = c * CHUNK;
#pragma unroll
    for (int j = 0; j < SCAT_I; j++) {
        int p = p0 + j * SCAT_T + threadIdx.x;
        if (p < N) {
            unsigned bb = rnd_bits(sk, s, (unsigned)p);
            unsigned b  = bb >> LOWBITS;
            unsigned slot = atomicAdd(&cursor[b], 1u);
            if (slot < CAPR)    // overflow P ~ 1e-20; clamped on read too
                g_pay[((size_t)(s * NBKT + b)) * CAPR + slot] =
                    ((unsigned long long)(bb & LOWMASK) << POSBITS)
                  | (unsigned long long)(unsigned)p;
        }
    }
}

// One block per segment: exclusive scan of 2048 bucket counts -> absolute bases.
__global__ void __launch_bounds__(1024)
rmi_scan(int N, int round) {
    int s = blockIdx.x, t = threadIdx.x;
    const unsigned* cur = &g_cursor[round][s * NBKT];
    unsigned c0 = cur[2 * t],     n0 = c0 > CAPR ? CAPR : c0;
    unsigned c1 = cur[2 * t + 1], n1 = c1 > CAPR ? CAPR : c1;
    unsigned tsum = n0 + n1;

    // exclusive scan of tsum over 1024 threads (shuffle + smem)
    int lane = t & 31, w = t >> 5;
    unsigned v = tsum;
#pragma unroll
    for (int o = 1; o < 32; o <<= 1) {
        unsigned u = __shfl_up_sync(0xffffffffu, v, o);
        if (lane >= o) v += u;
    }
    __shared__ unsigned wsums[32];
    if (lane == 31) wsums[w] = v;
    __syncthreads();
    if (w == 0) {
        unsigned x = wsums[lane];
#pragma unroll
        for (int o = 1; o < 32; o <<= 1) {
            unsigned u = __shfl_up_sync(0xffffffffu, x, o);
            if (lane >= o) x += u;
        }
        wsums[lane] = x - wsums[lane];   // exclusive warp offsets
    }
    __syncthreads();
    unsigned excl = wsums[w] + (v - tsum) + (unsigned)(s * N);
    g_base[round][s * NBKT + 2 * t]     = excl;
    g_base[round][s * NBKT + 2 * t + 1] = excl + n0;
}

// One CTA per (segment, bucket): stable pair sort of <=768 (low21 key, pos)
// pairs in 3 radix passes (RADIX_BITS=7), then 6 odd-even tie-fix sweeps.
template <int ROUND>
__global__ void __launch_bounds__(SORT_T)
rmi_bucket_sort(int N, unsigned* __restrict__ out) {
    int s = blockIdx.x >> BBITS, b = blockIdx.x & (NBKT - 1);
    int sb = s * NBKT + b;
    unsigned n = g_cursor[ROUND][sb];
    if (n > CAPR) n = CAPR;
    unsigned base = g_base[ROUND][sb];

    typedef cub::BlockRadixSort<unsigned, SORT_T, SORT_I, unsigned,
                                /*RADIX_BITS=*/7> Sorter;
    __shared__ union {
        typename Sorter::TempStorage ts;
        struct { unsigned k[CAPF]; unsigned v[CAPF]; } st;
    } sm;

    const unsigned long long* pay = &g_pay[(size_t)sb * CAPR];
    unsigned keys[SORT_I], vals[SORT_I];
#pragma unroll
    for (int k = 0; k < SORT_I; k++) {
        unsigned r = threadIdx.x * SORT_I + k;
        if (r < n) {
            unsigned long long pv = pay[r];
            keys[k] = (unsigned)(pv >> POSBITS);
            vals[k] = (unsigned)pv & POSMASK;
        } else {
            keys[k] = LOWMASK;       // pads: max key, pos > any real pos
            vals[k] = POSMASK;
        }
    }
    Sorter(sm.ts).Sort(keys, vals, 0, LOWBITS);   // stable, 3 passes

    __syncthreads();
#pragma unroll
    for (int k = 0; k < SORT_I; k++) {
        unsigned r = threadIdx.x * SORT_I + k;
        sm.st.k[r] = keys[k];
        sm.st.v[r] = vals[k];
    }
    __syncthreads();

    // tie-fix: equal low21 in same bucket == equal full 32-bit key -> order by
    // pos (stability). odd-even transposition, 6 sweeps (run>6: P ~ 1e-19).
    for (int ph = 0; ph < 6; ph++) {
        int par = ph & 1;
        for (int m = threadIdx.x; 2 * m + par + 1 < CAPF; m += SORT_T) {
            int r = 2 * m + par;
            if (sm.st.k[r] == sm.st.k[r + 1] && sm.st.v[r] > sm.st.v[r + 1]) {
                unsigned t = sm.st.v[r]; sm.st.v[r] = sm.st.v[r + 1]; sm.st.v[r + 1] = t;
            }
        }
        __syncthreads();
    }

    for (unsigned r = threadIdx.x; r < n; r += SORT_T) {
        unsigned pos = sm.st.v[r];
        unsigned val = (ROUND == 0) ? pos : __ldg(&g_v1[s * N + pos]);
        out[base + r] = val;
    }
}

// ============================================================================
// Parameter init
// ============================================================================
__global__ void rmi_init_params(const float* __restrict__ w1,
                                const float* __restrict__ b1,
                                const float* __restrict__ w2,
                                const float* __restrict__ b2) {
    int t = threadIdx.x;
    if (t < 64)       g_P[t] = w1[t];
    else if (t < 68)  g_P[t] = b1[t - 64];
    else if (t < 72)  g_P[t] = w2[t - 68];
    else if (t == 72) g_P[72] = b2[0];
    if (t < 73) { g_m[t] = 0.f; g_v[t] = 0.f; }
}

// ============================================================================
// Tiny-MLP helpers (all register-resident)
// ============================================================================
__device__ __forceinline__ void load8(const float* __restrict__ base, unsigned row,
                                      float* __restrict__ dst) {
    const float4* p = (const float4*)base + 2ull * row;
    float4 a = __ldg(p), b = __ldg(p + 1);
    dst[0] = a.x; dst[1] = a.y; dst[2] = a.z; dst[3] = a.w;
    dst[4] = b.x; dst[5] = b.y; dst[6] = b.z; dst[7] = b.w;
}

__device__ __forceinline__ float ftanh(float x) {
    float e = __expf(2.f * x);
    return 1.f - 2.f * __frcp_rn(e + 1.f);
}

// ============================================================================
// Fused per-step pass (FROZEN from the passing R8 kernel)
// ============================================================================
__global__ void __launch_bounds__(GNT, 2)
rmi_fused_step(const float* __restrict__ x, const float* __restrict__ y,
               const unsigned* __restrict__ pi, int N) {
    const int role = blockIdx.x & 1;
    const int b    = blockIdx.x >> 1;
    const int stride = HALFB * GNT;

    float P[73];
#pragma unroll
    for (int t = 0; t < 73; t++) P[t] = g_P[t];

    float acc[73];
#pragma unroll
    for (int t = 0; t < 73; t++) acc[t] = 0.f;
    float S = 0.f;

    int i = b * GNT + threadIdx.x;
    float cur[16], nxt[16];
    unsigned rown = 0;
    if (i < N) {
        unsigned r0 = role ? __ldg(pi + i) : (unsigned)i;
        load8(x, (unsigned)i, cur);
        load8(y, r0, cur + 8);
        int i1 = i + stride;
        if (i1 < N) rown = role ? __ldg(pi + i1) : (unsigned)i1;
    }

    for (; i < N; i += stride) {
        const int inx = i + stride;
        if (inx < N) {
            load8(x, (unsigned)inx, nxt);
            load8(y, rown, nxt + 8);
        }
        const int inx2 = inx + stride;
        unsigned rown2 = 0;
        if (inx2 < N) rown2 = role ? __ldg(pi + inx2) : (unsigned)inx2;

        float h[4];
        float s = P[72];
#pragma unroll
        for (int k = 0; k < 4; k++) {
            float u = P[64 + k];
#pragma unroll
            for (int j = 0; j < 16; j++) u = fmaf(P[k * 16 + j], cur[j], u);
            float hk = ftanh(u);
            h[k] = hk;
            s = fmaf(P[68 + k], hk, s);
        }
        float o = ftanh(s);
        float f = role ? 2.f * o : o;
        float w = __expf(f);
        S += w;

        float d = w * (1.f - o * o);
        acc[72] += d;
#pragma unroll
        for (int k = 0; k < 4; k++) {
            acc[68 + k] = fmaf(d, h[k], acc[68 + k]);
            float e = d * P[68 + k] * (1.f - h[k] * h[k]);
            acc[64 + k] += e;
#pragma unroll
            for (int j = 0; j < 16; j++)
                acc[k * 16 + j] = fmaf(e, cur[j], acc[k * 16 + j]);
        }

        if (inx < N) {
#pragma unroll
            for (int j = 0; j < 16; j++) cur[j] = nxt[j];
        }
        rown = rown2;
    }

#pragma unroll
    for (int t = 0; t < 73; t++) {
        float v = acc[t];
#pragma unroll
        for (int o = 16; o > 0; o >>= 1) v += __shfl_down_sync(0xffffffffu, v, o);
        acc[t] = v;
    }
    __shared__ float wsum[GNT / 32][73];
    int wid = threadIdx.x >> 5, lane = threadIdx.x & 31;
    if (lane == 0) {
#pragma unroll
        for (int t = 0; t < 73; t++) wsum[wid][t] = acc[t];
    }
    __syncthreads();
    if (threadIdx.x < 73) {
        float s = 0.f;
#pragma unroll
        for (int w = 0; w < GNT / 32; w++) s += wsum[w][threadIdx.x];
        g_partial[role][threadIdx.x][b] = s;
    }

    __shared__ double red[GNT];
    red[threadIdx.x] = (double)S;
    __syncthreads();
    for (int o = GNT / 2; o > 0; o >>= 1) {
        if (threadIdx.x < (unsigned)o) red[threadIdx.x] += red[threadIdx.x + o];
        __syncthreads();
    }
    if (threadIdx.x == 0) g_S[role][b] = red[0];
}

// ============================================================================
// Finalize (frozen)
// ============================================================================
__global__ void __launch_bounds__(1024)
rmi_finalize(int step, float bc1, float bc2, double logN) {
    __shared__ double red[256];
    __shared__ double sS[2];

    if (threadIdx.x < 256) {
        int role = threadIdx.x >> 7;
        int lane = threadIdx.x & 127;
        double s = 0.0;
        for (int bb = lane; bb < HALFB; bb += 128) s += g_S[role][bb];
        red[threadIdx.x] = s;
    }
    __syncthreads();
    for (int o = 64; o > 0; o >>= 1) {
        if (threadIdx.x < 256 && (threadIdx.x & 127) < o)
            red[threadIdx.x] += red[threadIdx.x + o];
        __syncthreads();
    }
    if (threadIdx.x == 0)   sS[0] = red[0];
    if (threadIdx.x == 128) sS[1] = red[128];
    __syncthreads();
    double S1 = sS[0], S2 = sS[1];

    int wid = threadIdx.x >> 5, lane = threadIdx.x & 31;
    for (int row = wid; row < 146; row += 32) {
        int role = row >= 73 ? 1 : 0;
        int p = role ? row - 73 : row;
        const float* src = &g_partial[role][p][0];
        double s = 0.0;
        for (int bb = lane; bb < HALFB; bb += 32) s += (double)__ldg(src + bb);
#pragma unroll
        for (int o = 16; o > 0; o >>= 1) s += __shfl_down_sync(0xffffffffu, s, o);
        if (lane == 0) g_G[role][p] = s;
    }
    __syncthreads();

    if (threadIdx.x == 0) {
        double t1 = log(S1) - logN;
        double t2 = 0.5 * (log(S2) - logN);
        g_losses[step] = (float)(t1 - t2);
    }
    if (threadIdx.x < 73) {
        int t = threadIdx.x;
        float g = (float)(g_G[1][t] / S2 - g_G[0][t] / S1);
        float m = 0.9f   * g_m[t] + 0.1f   * g;
        float v = 0.999f * g_v[t] + 0.001f * g * g;
        g_m[t] = m; g_v[t] = v;
        g_P[t] -= 1e-3f * (m / bc1) / (sqrtf(v / bc2) + 1e-8f);
    }
}

__global__ void rmi_write_out(float* __restrict__ out, int out_size) {
    for (int i = threadIdx.x; i < out_size; i += blockDim.x) {
        float v;
        if (out_size == NSTEPS)      v = g_losses[i];
        else if (out_size == 1)      v = g_losses[NSTEPS - 1];
        else {
            if (i == 0)              v = g_losses[NSTEPS - 1];
            else if (i <= NSTEPS)    v = g_losses[i - 1];
            else                     v = 0.f;
        }
        out[i] = v;
    }
}

// ============================================================================
// Host driver (graph-capturable: plain kernel launches only)
// ============================================================================
extern "C" void kernel_launch(void* const* d_in, const int* in_sizes, int n_in,
                              void* d_out, int out_size) {
    const float* x  = (const float*)d_in[0];
    const float* y  = (const float*)d_in[1];
    const float* w1 = (const float*)d_in[2];
    const float* b1 = (const float*)d_in[3];
    const float* w2 = (const float*)d_in[4];
    const float* b2 = (const float*)d_in[5];
    int N = in_sizes[0] / 8;
    if (N > MAXN) N = MAXN;

    rmi_init_params<<<1, 128>>>(w1, b1, w2, b2);

    // --- shuffle subkeys (host, input-independent, deterministic) ---
    // master key(42) = (0,42); fold-like split: key_s = tf(master,(0,s));
    // per round: new_key = tf(K,(0,0)), subkey = tf(K,(0,1)). 2 rounds for
    // N ~ 1M (ceil(3*log(N)/log(2^32)) = 2).
    SubKeys subk[2];
    for (int s = 0; s < NSEG; s++) {
        unsigned K0, K1;
        tf2x32(0u, 42u, 0u, (unsigned)s, K0, K1);
        for (int r = 0; r < 2; r++) {
            unsigned nk0, nk1, sb0, sb1;
            tf2x32(K0, K1, 0u, 0u, nk0, nk1);
            tf2x32(K0, K1, 0u, 1u, sb0, sb1);
            subk[r].k0[s] = sb0; subk[r].k1[s] = sb1;
            K0 = nk0; K1 = nk1;
        }
    }

    unsigned *v1p, *pp;
    cudaGetSymbolAddress((void**)&v1p, g_v1);
    cudaGetSymbolAddress((void**)&pp, g_perms);

    // --- permutation pipeline: 2 stable-sort rounds ---
    const int cps = (N + CHUNK - 1) / CHUNK;
    rmi_zero_cursors<<<(NSEG * NBKT * 2 + 511) / 512, 512>>>();
    rmi_scatter<<<NSEG * cps, SCAT_T>>>(subk[0], N, cps, 0);
    rmi_scan<<<NSEG, 1024>>>(N, 0);
    rmi_bucket_sort<0><<<NSEG << BBITS, SORT_T>>>(N, v1p);
    rmi_scatter<<<NSEG * cps, SCAT_T>>>(subk[1], N, cps, 1);
    rmi_scan<<<NSEG, 1024>>>(N, 1);
    rmi_bucket_sort<1><<<NSEG << BBITS, SORT_T>>>(N, pp);

    // --- 8 fused training steps ---
    const double logN = log((double)N);
    for (int s = 0; s < NSTEPS; s++) {
        const unsigned* pi = pp + (size_t)s * N;
        rmi_fused_step<<<2 * HALFB, GNT>>>(x, y, pi, N);
        double t = (double)(s + 1);
        float bc1 = (float)(1.0 - pow(0.9,   t));
        float bc2 = (float)(1.0 - pow(0.999, t));
        rmi_finalize<<<1, 1024>>>(s, bc1, bc2, logN);
    }

    rmi_write_out<<<1, 32>>>((float*)d_out, out_size);
}

// round 11
// speedup vs baseline: 1.6506x; 1.2508x over previous
#include <cuda_runtime.h>
#include <cstdint>
#include <math.h>
#include <cub/block/block_radix_sort.cuh>

// ============================================================================
// Problem constants
// ============================================================================
#define MAXN    1048576
#define NSTEPS  8
#define NSEG    8               // 8 permutations (one per training step)
#define HALFB   512             // blocks per role in step kernel
#define GNT     128             // threads per block in step kernel

// --- permutation sort configuration ---
#define BBITS   11              // MSD bucket bits
#define NBKT    (1 << BBITS)    // 2048 buckets per segment
#define LOWBITS (32 - BBITS)    // 21 low key bits
#define LOWMASK ((1u << LOWBITS) - 1u)
#define POSBITS 21              // position field in payload (N <= 2^20)
#define POSMASK ((1u << POSBITS) - 1u)
#define CAPR    768             // fixed region capacity (avg 512, +11 sigma)
#define SORT_T  128
#define SORT_I  6               // 128*6 = 768 = CAPR
#define CAPF    (SORT_T * SORT_I)
#define SCAT_T  512
#define SCAT_I  16
#define CHUNK   (SCAT_T * SCAT_I)   // 8192 elements per scatter CTA
#define CPAD    8               // cursor padding (32B stride -> no same-sector atomics)

struct SubKeys { unsigned k0[NSEG]; unsigned k1[NSEG]; };

// ============================================================================
// Static device scratch (no dynamic allocation allowed)
// ============================================================================
__device__ __align__(256) unsigned long long g_pay[NSEG * NBKT * (size_t)CAPR];
__device__ __align__(256) unsigned           g_v1[NSEG * MAXN];    // round-1 result
__device__ __align__(256) unsigned           g_perms[NSEG * MAXN]; // final permutations
__device__ unsigned g_cursor[2][NSEG * NBKT * CPAD];   // padded bucket cursors
__device__ unsigned g_base[2][NSEG * NBKT];            // absolute output bases

__device__ float  g_P[73];                    // [0..63]=w1, [64..67]=b1, [68..71]=w2, [72]=b2
__device__ float  g_m[73];
__device__ float  g_v[73];
__device__ float  g_partial[2][73][HALFB];
__device__ double g_S[2][HALFB];
__device__ double g_G[2][73];
__device__ double g_Stot[2];
__device__ float  g_losses[NSTEPS];

// ============================================================================
// Threefry2x32 — exact JAX implementation (20 rounds, 5 key injections)
// ============================================================================
__host__ __device__ __forceinline__ void tf2x32(unsigned k0, unsigned k1,
                                                unsigned c0, unsigned c1,
                                                unsigned &o0, unsigned &o1) {
    unsigned ks0 = k0, ks1 = k1, ks2 = k0 ^ k1 ^ 0x1BD11BDAu;
    unsigned x0 = c0 + ks0, x1 = c1 + ks1;
#define TFR(r) { x0 += x1; x1 = (x1 << (r)) | (x1 >> (32 - (r))); x1 ^= x0; }
    TFR(13) TFR(15) TFR(26) TFR(6)
    x0 += ks1; x1 += ks2 + 1u;
    TFR(17) TFR(29) TFR(16) TFR(24)
    x0 += ks2; x1 += ks0 + 2u;
    TFR(13) TFR(15) TFR(26) TFR(6)
    x0 += ks0; x1 += ks1 + 3u;
    TFR(17) TFR(29) TFR(16) TFR(24)
    x0 += ks1; x1 += ks2 + 4u;
    TFR(13) TFR(15) TFR(26) TFR(6)
    x0 += ks2; x1 += ks0 + 5u;
#undef TFR
    o0 = x0; o1 = x1;
}

__device__ __forceinline__ unsigned rnd_bits(const SubKeys& sk, int s, unsigned p) {
    unsigned a, b;
    tf2x32(sk.k0[s], sk.k1[s], 0u, p, a, b);
    return a ^ b;   // partitionable-threefry 32-bit random_bits
}

// ============================================================================
// Fused init: params + Adam state (block 0) AND cursor zeroing (all blocks).
// Single launch so the profiler's fixed capture index lands on bucket_sort<0>.
// ============================================================================
__global__ void rmi_init_zero(const float* __restrict__ w1,
                              const float* __restrict__ b1,
                              const float* __restrict__ w2,
                              const float* __restrict__ b2) {
    int gid = blockIdx.x * blockDim.x + threadIdx.x;
    int tot = NSEG * NBKT * CPAD;
    for (int i = gid; i < tot; i += gridDim.x * blockDim.x) {
        g_cursor[0][i] = 0; g_cursor[1][i] = 0;
    }
    if (blockIdx.x == 0) {
        int t = threadIdx.x;
        if (t < 64)       g_P[t] = w1[t];
        else if (t < 68)  g_P[t] = b1[t - 64];
        else if (t < 72)  g_P[t] = w2[t - 68];
        else if (t == 72) g_P[72] = b2[0];
        if (t < 73) { g_m[t] = 0.f; g_v[t] = 0.f; }
    }
}

// ============================================================================
// Permutation pipeline (logic frozen from passing R9; cursors padded)
// ============================================================================
__global__ void __launch_bounds__(SCAT_T)
rmi_scatter(SubKeys sk, int N, int cps, int round) {
    int s = blockIdx.x / cps, c = blockIdx.x % cps;
    unsigned* cursor = &g_cursor[round][s * NBKT * CPAD];
    int p0 = c * CHUNK;
#pragma unroll
    for (int j = 0; j < SCAT_I; j++) {
        int p = p0 + j * SCAT_T + threadIdx.x;
        if (p < N) {
            unsigned bb = rnd_bits(sk, s, (unsigned)p);
            unsigned b  = bb >> LOWBITS;
            unsigned slot = atomicAdd(&cursor[b * CPAD], 1u);
            if (slot < CAPR)    // overflow P ~ 1e-20; clamped on read too
                g_pay[((size_t)(s * NBKT + b)) * CAPR + slot] =
                    ((unsigned long long)(bb & LOWMASK) << POSBITS)
                  | (unsigned long long)(unsigned)p;
        }
    }
}

// One block per segment: exclusive scan of 2048 bucket counts -> absolute bases.
__global__ void __launch_bounds__(1024)
rmi_scan(int N, int round) {
    int s = blockIdx.x, t = threadIdx.x;
    const unsigned* cur = &g_cursor[round][s * NBKT * CPAD];
    unsigned c0 = cur[(2 * t) * CPAD],     n0 = c0 > CAPR ? CAPR : c0;
    unsigned c1 = cur[(2 * t + 1) * CPAD], n1 = c1 > CAPR ? CAPR : c1;
    unsigned tsum = n0 + n1;

    int lane = t & 31, w = t >> 5;
    unsigned v = tsum;
#pragma unroll
    for (int o = 1; o < 32; o <<= 1) {
        unsigned u = __shfl_up_sync(0xffffffffu, v, o);
        if (lane >= o) v += u;
    }
    __shared__ unsigned wsums[32];
    if (lane == 31) wsums[w] = v;
    __syncthreads();
    if (w == 0) {
        unsigned x = wsums[lane];
#pragma unroll
        for (int o = 1; o < 32; o <<= 1) {
            unsigned u = __shfl_up_sync(0xffffffffu, x, o);
            if (lane >= o) x += u;
        }
        wsums[lane] = x - wsums[lane];   // exclusive warp offsets
    }
    __syncthreads();
    unsigned excl = wsums[w] + (v - tsum) + (unsigned)(s * N);
    g_base[round][s * NBKT + 2 * t]     = excl;
    g_base[round][s * NBKT + 2 * t + 1] = excl + n0;
}

// One CTA per (segment, bucket): stable pair sort of <=768 (low21 key, pos)
// pairs in 3 radix passes (RADIX_BITS=7), then 6 odd-even tie-fix sweeps.
template <int ROUND>
__global__ void __launch_bounds__(SORT_T)
rmi_bucket_sort(int N, unsigned* __restrict__ out) {
    int s = blockIdx.x >> BBITS, b = blockIdx.x & (NBKT - 1);
    int sb = s * NBKT + b;
    unsigned n = g_cursor[ROUND][sb * CPAD];
    if (n > CAPR) n = CAPR;
    unsigned base = g_base[ROUND][sb];

    typedef cub::BlockRadixSort<unsigned, SORT_T, SORT_I, unsigned,
                                /*RADIX_BITS=*/7> Sorter;
    __shared__ union {
        typename Sorter::TempStorage ts;
        struct { unsigned k[CAPF]; unsigned v[CAPF]; } st;
    } sm;

    const unsigned long long* pay = &g_pay[(size_t)sb * CAPR];
    unsigned keys[SORT_I], vals[SORT_I];
#pragma unroll
    for (int k = 0; k < SORT_I; k++) {
        unsigned r = threadIdx.x * SORT_I + k;
        if (r < n) {
            unsigned long long pv = pay[r];
            keys[k] = (unsigned)(pv >> POSBITS);
            vals[k] = (unsigned)pv & POSMASK;
        } else {
            keys[k] = LOWMASK;       // pads: max key, pos > any real pos
            vals[k] = POSMASK;
        }
    }
    Sorter(sm.ts).Sort(keys, vals, 0, LOWBITS);   // stable, 3 passes

    __syncthreads();
#pragma unroll
    for (int k = 0; k < SORT_I; k++) {
        unsigned r = threadIdx.x * SORT_I + k;
        sm.st.k[r] = keys[k];
        sm.st.v[r] = vals[k];
    }
    __syncthreads();

    // tie-fix: equal low21 in same bucket == equal full 32-bit key -> order by
    // pos (stability). odd-even transposition, 6 sweeps (run>6: P ~ 1e-19).
    for (int ph = 0; ph < 6; ph++) {
        int par = ph & 1;
        for (int m = threadIdx.x; 2 * m + par + 1 < CAPF; m += SORT_T) {
            int r = 2 * m + par;
            if (sm.st.k[r] == sm.st.k[r + 1] && sm.st.v[r] > sm.st.v[r + 1]) {
                unsigned t = sm.st.v[r]; sm.st.v[r] = sm.st.v[r + 1]; sm.st.v[r + 1] = t;
            }
        }
        __syncthreads();
    }

    for (unsigned r = threadIdx.x; r < n; r += SORT_T) {
        unsigned pos = sm.st.v[r];
        unsigned val = (ROUND == 0) ? pos : __ldg(&g_v1[s * N + pos]);
        out[base + r] = val;
    }
}

// ============================================================================
// Tiny-MLP helpers
// ============================================================================
__device__ __forceinline__ void load8(const float* __restrict__ base, unsigned row,
                                      float* __restrict__ dst) {
    const float4* p = (const float4*)base + 2ull * row;
    float4 a = __ldg(p), b = __ldg(p + 1);
    dst[0] = a.x; dst[1] = a.y; dst[2] = a.z; dst[3] = a.w;
    dst[4] = b.x; dst[5] = b.y; dst[6] = b.z; dst[7] = b.w;
}

__device__ __forceinline__ float ftanh(float x) {
    float e = __expf(2.f * x);
    return 1.f - 2.f * __frcp_rn(e + 1.f);
}

// ============================================================================
// Fused per-step pass — MINIMAL register variant (spill-proof):
// P in shared (broadcast LDS), only acc[73]+inp[16] in registers (~115 regs).
// One-ahead pi prefetch only; no data pipeline.
// ============================================================================
__global__ void __launch_bounds__(GNT)
rmi_fused_step(const float* __restrict__ x, const float* __restrict__ y,
               const unsigned* __restrict__ pi, int N) {
    const int role = blockIdx.x & 1;
    const int b    = blockIdx.x >> 1;
    const int stride = HALFB * GNT;

    __shared__ float Ps[73];
    if (threadIdx.x < 73) Ps[threadIdx.x] = g_P[threadIdx.x];
    __syncthreads();

    float acc[73];
#pragma unroll
    for (int t = 0; t < 73; t++) acc[t] = 0.f;
    float S = 0.f;

    int i0 = b * GNT + threadIdx.x;
    unsigned rown = 0;
    if (i0 < N) rown = role ? __ldg(pi + i0) : (unsigned)i0;

    for (int i = i0; i < N; i += stride) {
        unsigned row = rown;
        int inx = i + stride;
        if (inx < N) rown = role ? __ldg(pi + inx) : (unsigned)inx;

        float inp[16];
        load8(x, (unsigned)i, inp);
        load8(y, row, inp + 8);

        float h[4];
        float s = Ps[72];
#pragma unroll
        for (int k = 0; k < 4; k++) {
            float u = Ps[64 + k];
#pragma unroll
            for (int j = 0; j < 16; j++) u = fmaf(Ps[k * 16 + j], inp[j], u);
            float hk = ftanh(u);
            h[k] = hk;
            s = fmaf(Ps[68 + k], hk, s);
        }
        float o = ftanh(s);
        float f = role ? 2.f * o : o;       // ALPHA=2: f2 = 2*est, f1 = est
        float w = __expf(f);                // no shift needed: |f| <= 2
        S += w;

        float d = w * (1.f - o * o);
        acc[72] += d;
#pragma unroll
        for (int k = 0; k < 4; k++) {
            acc[68 + k] = fmaf(d, h[k], acc[68 + k]);
            float e = d * Ps[68 + k] * (1.f - h[k] * h[k]);
            acc[64 + k] += e;
#pragma unroll
            for (int j = 0; j < 16; j++)
                acc[k * 16 + j] = fmaf(e, inp[j], acc[k * 16 + j]);
        }
    }

    // --- deterministic block reduction of 73 accumulators ---
#pragma unroll
    for (int t = 0; t < 73; t++) {
        float v = acc[t];
#pragma unroll
        for (int o = 16; o > 0; o >>= 1) v += __shfl_down_sync(0xffffffffu, v, o);
        acc[t] = v;
    }
    __shared__ float wsum[GNT / 32][73];
    int wid = threadIdx.x >> 5, lane = threadIdx.x & 31;
    if (lane == 0) {
#pragma unroll
        for (int t = 0; t < 73; t++) wsum[wid][t] = acc[t];
    }
    __syncthreads();
    if (threadIdx.x < 73) {
        float s = 0.f;
#pragma unroll
        for (int w = 0; w < GNT / 32; w++) s += wsum[w][threadIdx.x];
        g_partial[role][threadIdx.x][b] = s;
    }

    // --- deterministic block reduction of S (fp64 tree) ---
    __shared__ double red[GNT];
    red[threadIdx.x] = (double)S;
    __syncthreads();
    for (int o = GNT / 2; o > 0; o >>= 1) {
        if (threadIdx.x < (unsigned)o) red[threadIdx.x] += red[threadIdx.x + o];
        __syncthreads();
    }
    if (threadIdx.x == 0) g_S[role][b] = red[0];
}

// ============================================================================
// Parallel reduction: 148 blocks. Rows 0..145 -> grad sums; 146/147 -> S sums.
// Fixed-shape fp64 trees -> bit-deterministic.
// ============================================================================
__global__ void __launch_bounds__(256)
rmi_reduce(void) {
    int row = blockIdx.x, t = threadIdx.x;
    __shared__ double red[256];
    double s = 0.0;
    if (row < 146) {
        int role = row >= 73 ? 1 : 0;
        int p = role ? row - 73 : row;
        const float* src = &g_partial[role][p][0];
        for (int bb = t; bb < HALFB; bb += 256) s += (double)__ldg(src + bb);
    } else {
        int role = row - 146;
        for (int bb = t; bb < HALFB; bb += 256) s += g_S[role][bb];
    }
    red[t] = s;
    __syncthreads();
    for (int o = 128; o > 0; o >>= 1) {
        if (t < o) red[t] += red[t + o];
        __syncthreads();
    }
    if (t == 0) {
        if (row < 146) {
            int role = row >= 73 ? 1 : 0;
            int p = role ? row - 73 : row;
            g_G[role][p] = red[0];
        } else {
            g_Stot[row - 146] = red[0];
        }
    }
}

// ============================================================================
// Adam + loss (tiny)
// ============================================================================
__global__ void __launch_bounds__(128)
rmi_adam(int step, float bc1, float bc2, double logN) {
    double S1 = g_Stot[0], S2 = g_Stot[1];
    if (threadIdx.x == 0) {
        double t1 = log(S1) - logN;              // lse(f1) - logN
        double t2 = 0.5 * (log(S2) - logN);      // (lse(f2) - logN)/ALPHA
        g_losses[step] = (float)(t1 - t2);
    }
    if (threadIdx.x < 73) {
        int t = threadIdx.x;
        float g = (float)(g_G[1][t] / S2 - g_G[0][t] / S1);
        float m = 0.9f   * g_m[t] + 0.1f   * g;
        float v = 0.999f * g_v[t] + 0.001f * g * g;
        g_m[t] = m; g_v[t] = v;
        g_P[t] -= 1e-3f * (m / bc1) / (sqrtf(v / bc2) + 1e-8f);
    }
}

__global__ void rmi_write_out(float* __restrict__ out, int out_size) {
    for (int i = threadIdx.x; i < out_size; i += blockDim.x) {
        float v;
        if (out_size == NSTEPS)      v = g_losses[i];
        else if (out_size == 1)      v = g_losses[NSTEPS - 1];
        else {
            if (i == 0)              v = g_losses[NSTEPS - 1];
            else if (i <= NSTEPS)    v = g_losses[i - 1];
            else                     v = 0.f;
        }
        out[i] = v;
    }
}

// ============================================================================
// Host driver (graph-capturable: plain kernel launches only)
// ============================================================================
extern "C" void kernel_launch(void* const* d_in, const int* in_sizes, int n_in,
                              void* d_out, int out_size) {
    const float* x  = (const float*)d_in[0];
    const float* y  = (const float*)d_in[1];
    const float* w1 = (const float*)d_in[2];
    const float* b1 = (const float*)d_in[3];
    const float* w2 = (const float*)d_in[4];
    const float* b2 = (const float*)d_in[5];
    int N = in_sizes[0] / 8;
    if (N > MAXN) N = MAXN;

    // --- shuffle subkeys (host, input-independent, deterministic) ---
    // master key(42) = (0,42); fold-like split: key_s = tf(master,(0,s));
    // per round: new_key = tf(K,(0,0)), subkey = tf(K,(0,1)). 2 rounds for
    // N ~ 1M (ceil(3*log(N)/log(2^32)) = 2).
    SubKeys subk[2];
    for (int s = 0; s < NSEG; s++) {
        unsigned K0, K1;
        tf2x32(0u, 42u, 0u, (unsigned)s, K0, K1);
        for (int r = 0; r < 2; r++) {
            unsigned nk0, nk1, sb0, sb1;
            tf2x32(K0, K1, 0u, 0u, nk0, nk1);
            tf2x32(K0, K1, 0u, 1u, sb0, sb1);
            subk[r].k0[s] = sb0; subk[r].k1[s] = sb1;
            K0 = nk0; K1 = nk1;
        }
    }

    unsigned *v1p, *pp;
    cudaGetSymbolAddress((void**)&v1p, g_v1);
    cudaGetSymbolAddress((void**)&pp, g_perms);

    // --- launches: index 3 == bucket_sort<0> (the profiler's capture slot) ---
    const int cps = (N + CHUNK - 1) / CHUNK;
    rmi_init_zero<<<64, 512>>>(w1, b1, w2, b2);                 // 0
    rmi_scatter<<<NSEG * cps, SCAT_T>>>(subk[0], N, cps, 0);    // 1
    rmi_scan<<<NSEG, 1024>>>(N, 0);                             // 2
    rmi_bucket_sort<0><<<NSEG << BBITS, SORT_T>>>(N, v1p);      // 3  <- profiled
    rmi_scatter<<<NSEG * cps, SCAT_T>>>(subk[1], N, cps, 1);    // 4
    rmi_scan<<<NSEG, 1024>>>(N, 1);                             // 5
    rmi_bucket_sort<1><<<NSEG << BBITS, SORT_T>>>(N, pp);       // 6

    // --- 8 fused training steps ---
    const double logN = log((double)N);
    for (int s = 0; s < NSTEPS; s++) {
        const unsigned* pi = pp + (size_t)s * N;
        rmi_fused_step<<<2 * HALFB, GNT>>>(x, y, pi, N);
        rmi_reduce<<<148, 256>>>();
        double t = (double)(s + 1);
        float bc1 = (float)(1.0 - pow(0.9,   t));
        float bc2 = (float)(1.0 - pow(0.999, t));
        rmi_adam<<<1, 128>>>(s, bc1, bc2, logN);
    }

    rmi_write_out<<<1, 32>>>((float*)d_out, out_size);
}

// round 12
// speedup vs baseline: 2.4493x; 1.4839x over previous
#include <cuda_runtime.h>
#include <cstdint>
#include <math.h>

// ============================================================================
// Problem constants
// ============================================================================
#define MAXN    1048576
#define NSTEPS  8
#define NSEG    8               // 8 permutations (one per training step)
#define HALFB   512             // blocks per role in step kernel
#define GNT     128             // threads per block in step kernel

// --- permutation sort configuration ---
#define BBITS   11              // MSD bucket bits
#define NBKT    (1 << BBITS)    // 2048 buckets per segment
#define LOWBITS (32 - BBITS)    // 21 low key bits
#define LOWMASK ((1u << LOWBITS) - 1u)
#define POSBITS 21              // position field in payload (N <= 2^20)
#define POSMASK ((1u << POSBITS) - 1u)
#define CAPR    768             // fixed region capacity (avg 512, +11 sigma)
#define SORT_T  128
#define SORT_I  6               // 128*6 = 768 = CAPR
#define CAPF    (SORT_T * SORT_I)
#define SUBB    8               // in-bucket counting-sort bits (key bits [13,21))
#define NSUB    (1 << SUBB)     // 256 sub-buckets, avg 3 elements each
#define M34     ((1ull << 34) - 1ull)   // residue: (rem13 key << 21) | pos
#define SCAT_T  512
#define SCAT_I  16
#define CHUNK   (SCAT_T * SCAT_I)   // 8192 elements per scatter CTA
#define CPAD    8               // cursor padding (32B stride -> no same-sector atomics)

struct SubKeys { unsigned k0[NSEG]; unsigned k1[NSEG]; };

// ============================================================================
// Static device scratch (no dynamic allocation allowed)
// ============================================================================
__device__ __align__(256) unsigned long long g_pay[NSEG * NBKT * (size_t)CAPR];
__device__ __align__(256) unsigned           g_v1[NSEG * MAXN];    // round-1 result
__device__ __align__(256) unsigned           g_perms[NSEG * MAXN]; // final permutations
__device__ unsigned g_cursor[2][NSEG * NBKT * CPAD];   // padded bucket cursors
__device__ unsigned g_base[2][NSEG * NBKT];            // absolute output bases

__device__ float  g_P[73];                    // [0..63]=w1, [64..67]=b1, [68..71]=w2, [72]=b2
__device__ float  g_m[73];
__device__ float  g_v[73];
__device__ float  g_partial[2][73][HALFB];
__device__ double g_S[2][HALFB];
__device__ double g_G[2][73];
__device__ double g_Stot[2];
__device__ float  g_losses[NSTEPS];

// ============================================================================
// Threefry2x32 — exact JAX implementation (20 rounds, 5 key injections)
// ============================================================================
__host__ __device__ __forceinline__ void tf2x32(unsigned k0, unsigned k1,
                                                unsigned c0, unsigned c1,
                                                unsigned &o0, unsigned &o1) {
    unsigned ks0 = k0, ks1 = k1, ks2 = k0 ^ k1 ^ 0x1BD11BDAu;
    unsigned x0 = c0 + ks0, x1 = c1 + ks1;
#define TFR(r) { x0 += x1; x1 = (x1 << (r)) | (x1 >> (32 - (r))); x1 ^= x0; }
    TFR(13) TFR(15) TFR(26) TFR(6)
    x0 += ks1; x1 += ks2 + 1u;
    TFR(17) TFR(29) TFR(16) TFR(24)
    x0 += ks2; x1 += ks0 + 2u;
    TFR(13) TFR(15) TFR(26) TFR(6)
    x0 += ks0; x1 += ks1 + 3u;
    TFR(17) TFR(29) TFR(16) TFR(24)
    x0 += ks1; x1 += ks2 + 4u;
    TFR(13) TFR(15) TFR(26) TFR(6)
    x0 += ks2; x1 += ks0 + 5u;
#undef TFR
    o0 = x0; o1 = x1;
}

__device__ __forceinline__ unsigned rnd_bits(const SubKeys& sk, int s, unsigned p) {
    unsigned a, b;
    tf2x32(sk.k0[s], sk.k1[s], 0u, p, a, b);
    return a ^ b;   // partitionable-threefry 32-bit random_bits
}

// ============================================================================
// Fused init: params + Adam state (block 0) AND cursor zeroing (all blocks).
// ============================================================================
__global__ void rmi_init_zero(const float* __restrict__ w1,
                              const float* __restrict__ b1,
                              const float* __restrict__ w2,
                              const float* __restrict__ b2) {
    int gid = blockIdx.x * blockDim.x + threadIdx.x;
    int tot = NSEG * NBKT * CPAD;
    for (int i = gid; i < tot; i += gridDim.x * blockDim.x) {
        g_cursor[0][i] = 0; g_cursor[1][i] = 0;
    }
    if (blockIdx.x == 0) {
        int t = threadIdx.x;
        if (t < 64)       g_P[t] = w1[t];
        else if (t < 68)  g_P[t] = b1[t - 64];
        else if (t < 72)  g_P[t] = w2[t - 68];
        else if (t == 72) g_P[72] = b2[0];
        if (t < 73) { g_m[t] = 0.f; g_v[t] = 0.f; }
    }
}

// ============================================================================
// Permutation pipeline (scatter + scan frozen from R11 passer)
// ============================================================================
__global__ void __launch_bounds__(SCAT_T)
rmi_scatter(SubKeys sk, int N, int cps, int round) {
    int s = blockIdx.x / cps, c = blockIdx.x % cps;
    unsigned* cursor = &g_cursor[round][s * NBKT * CPAD];
    int p0 = c * CHUNK;
#pragma unroll
    for (int j = 0; j < SCAT_I; j++) {
        int p = p0 + j * SCAT_T + threadIdx.x;
        if (p < N) {
            unsigned bb = rnd_bits(sk, s, (unsigned)p);
            unsigned b  = bb >> LOWBITS;
            unsigned slot = atomicAdd(&cursor[b * CPAD], 1u);
            if (slot < CAPR)    // overflow P ~ 1e-20; clamped on read too
                g_pay[((size_t)(s * NBKT + b)) * CAPR + slot] =
                    ((unsigned long long)(bb & LOWMASK) << POSBITS)
                  | (unsigned long long)(unsigned)p;
        }
    }
}

// One block per segment: exclusive scan of 2048 bucket counts -> absolute bases.
__global__ void __launch_bounds__(1024)
rmi_scan(int N, int round) {
    int s = blockIdx.x, t = threadIdx.x;
    const unsigned* cur = &g_cursor[round][s * NBKT * CPAD];
    unsigned c0 = cur[(2 * t) * CPAD],     n0 = c0 > CAPR ? CAPR : c0;
    unsigned c1 = cur[(2 * t + 1) * CPAD], n1 = c1 > CAPR ? CAPR : c1;
    unsigned tsum = n0 + n1;

    int lane = t & 31, w = t >> 5;
    unsigned v = tsum;
#pragma unroll
    for (int o = 1; o < 32; o <<= 1) {
        unsigned u = __shfl_up_sync(0xffffffffu, v, o);
        if (lane >= o) v += u;
    }
    __shared__ unsigned wsums[32];
    if (lane == 31) wsums[w] = v;
    __syncthreads();
    if (w == 0) {
        unsigned x = wsums[lane];
#pragma unroll
        for (int o = 1; o < 32; o <<= 1) {
            unsigned u = __shfl_up_sync(0xffffffffu, x, o);
            if (lane >= o) x += u;
        }
        wsums[lane] = x - wsums[lane];   // exclusive warp offsets
    }
    __syncthreads();
    unsigned excl = wsums[w] + (v - tsum) + (unsigned)(s * N);
    g_base[round][s * NBKT + 2 * t]     = excl;
    g_base[round][s * NBKT + 2 * t + 1] = excl + n0;
}

// ============================================================================
// In-bucket sort v2: counting sort by key bits [13,21) into 256 sub-buckets
// (avg 3 elems), then serial insertion sort per run on the unique 34-bit
// residue (rem13 key, pos21). Unique residues -> exact stable (key,pos) order.
// ~8 shared ops/element vs ~30 for BlockRadixSort+odd-even; 9 KB smem.
// ============================================================================
template <int ROUND>
__global__ void __launch_bounds__(SORT_T)
rmi_bucket_sort(int N, unsigned* __restrict__ out) {
    int s = blockIdx.x >> BBITS, b = blockIdx.x & (NBKT - 1);
    int sb = s * NBKT + b;
    unsigned n = g_cursor[ROUND][sb * CPAD];
    if (n > CAPR) n = CAPR;
    unsigned base = g_base[ROUND][sb];

    __shared__ unsigned long long buf[CAPF];   // 6 KB
    __shared__ unsigned cnt[NSUB];             // original counts (preserved)
    __shared__ unsigned off[NSUB];             // run starts
    __shared__ unsigned cur[NSUB];             // atomic cursors
    __shared__ unsigned ws4[4];

    const int tid = threadIdx.x;
    for (int i = tid; i < NSUB; i += SORT_T) cnt[i] = 0;
    __syncthreads();

    // load payloads (coalesced over filled region) + count sub-buckets
    const unsigned long long* pay = &g_pay[(size_t)sb * CAPR];
    unsigned long long v[SORT_I];
#pragma unroll
    for (int k = 0; k < SORT_I; k++) {
        unsigned r = (unsigned)(k * SORT_T + tid);
        if (r < n) {
            v[k] = pay[r];
            atomicAdd(&cnt[(unsigned)(v[k] >> 34)], 1u);
        } else v[k] = ~0ull;
    }
    __syncthreads();

    // exclusive scan of 256 counts (2 per thread, shuffle + 4-warp combine)
    {
        unsigned a0 = cnt[2 * tid], a1 = cnt[2 * tid + 1];
        unsigned tsum = a0 + a1;
        int lane = tid & 31, w = tid >> 5;
        unsigned sv = tsum;
#pragma unroll
        for (int o = 1; o < 32; o <<= 1) {
            unsigned u = __shfl_up_sync(0xffffffffu, sv, o);
            if (lane >= o) sv += u;
        }
        if (lane == 31) ws4[w] = sv;
        __syncthreads();
        unsigned wo = 0;
        for (int w2 = 0; w2 < 4; w2++) if (w2 < w) wo += ws4[w2];
        unsigned excl = wo + sv - tsum;
        off[2 * tid] = excl;       cur[2 * tid] = excl;
        off[2 * tid + 1] = excl + a0; cur[2 * tid + 1] = excl + a0;
    }
    __syncthreads();

    // scatter 34-bit residues into sub-bucket runs (order scrambled; fixed below)
#pragma unroll
    for (int k = 0; k < SORT_I; k++) {
        unsigned r = (unsigned)(k * SORT_T + tid);
        if (r < n) {
            unsigned sub = (unsigned)(v[k] >> 34);
            unsigned slot = atomicAdd(&cur[sub], 1u);
            buf[slot] = v[k] & M34;
        }
    }
    __syncthreads();

    // serial insertion sort per run (avg len 3; unique values -> exact order)
    for (int sub = tid; sub < NSUB; sub += SORT_T) {
        unsigned b0 = off[sub], L = cnt[sub];
        for (unsigned i = 1; i < L; i++) {
            unsigned long long key = buf[b0 + i];
            int j = (int)i - 1;
            while (j >= 0 && buf[b0 + j] > key) {
                buf[b0 + j + 1] = buf[b0 + j];
                j--;
            }
            buf[b0 + j + 1] = key;
        }
    }
    __syncthreads();

    // emit permuted values
    for (unsigned r = tid; r < n; r += SORT_T) {
        unsigned pos = (unsigned)buf[r] & POSMASK;
        unsigned val = (ROUND == 0) ? pos : __ldg(&g_v1[s * N + pos]);
        out[base + r] = val;
    }
}

// ============================================================================
// Tiny-MLP helpers
// ============================================================================
__device__ __forceinline__ void load8(const float* __restrict__ base, unsigned row,
                                      float* __restrict__ dst) {
    const float4* p = (const float4*)base + 2ull * row;
    float4 a = __ldg(p), b = __ldg(p + 1);
    dst[0] = a.x; dst[1] = a.y; dst[2] = a.z; dst[3] = a.w;
    dst[4] = b.x; dst[5] = b.y; dst[6] = b.z; dst[7] = b.w;
}

__device__ __forceinline__ float ftanh(float x) {
    float e = __expf(2.f * x);
    return 1.f - 2.f * __frcp_rn(e + 1.f);
}

// ============================================================================
// Fused per-step pass — minimal-register variant (FROZEN from R11 passer)
// ============================================================================
__global__ void __launch_bounds__(GNT)
rmi_fused_step(const float* __restrict__ x, const float* __restrict__ y,
               const unsigned* __restrict__ pi, int N) {
    const int role = blockIdx.x & 1;
    const int b    = blockIdx.x >> 1;
    const int stride = HALFB * GNT;

    __shared__ float Ps[73];
    if (threadIdx.x < 73) Ps[threadIdx.x] = g_P[threadIdx.x];
    __syncthreads();

    float acc[73];
#pragma unroll
    for (int t = 0; t < 73; t++) acc[t] = 0.f;
    float S = 0.f;

    int i0 = b * GNT + threadIdx.x;
    unsigned rown = 0;
    if (i0 < N) rown = role ? __ldg(pi + i0) : (unsigned)i0;

    for (int i = i0; i < N; i += stride) {
        unsigned row = rown;
        int inx = i + stride;
        if (inx < N) rown = role ? __ldg(pi + inx) : (unsigned)inx;

        float inp[16];
        load8(x, (unsigned)i, inp);
        load8(y, row, inp + 8);

        float h[4];
        float s = Ps[72];
#pragma unroll
        for (int k = 0; k < 4; k++) {
            float u = Ps[64 + k];
#pragma unroll
            for (int j = 0; j < 16; j++) u = fmaf(Ps[k * 16 + j], inp[j], u);
            float hk = ftanh(u);
            h[k] = hk;
            s = fmaf(Ps[68 + k], hk, s);
        }
        float o = ftanh(s);
        float f = role ? 2.f * o : o;       // ALPHA=2: f2 = 2*est, f1 = est
        float w = __expf(f);                // no shift needed: |f| <= 2
        S += w;

        float d = w * (1.f - o * o);
        acc[72] += d;
#pragma unroll
        for (int k = 0; k < 4; k++) {
            acc[68 + k] = fmaf(d, h[k], acc[68 + k]);
            float e = d * Ps[68 + k] * (1.f - h[k] * h[k]);
            acc[64 + k] += e;
#pragma unroll
            for (int j = 0; j < 16; j++)
                acc[k * 16 + j] = fmaf(e, inp[j], acc[k * 16 + j]);
        }
    }

    // --- deterministic block reduction of 73 accumulators ---
#pragma unroll
    for (int t = 0; t < 73; t++) {
        float v = acc[t];
#pragma unroll
        for (int o = 16; o > 0; o >>= 1) v += __shfl_down_sync(0xffffffffu, v, o);
        acc[t] = v;
    }
    __shared__ float wsum[GNT / 32][73];
    int wid = threadIdx.x >> 5, lane = threadIdx.x & 31;
    if (lane == 0) {
#pragma unroll
        for (int t = 0; t < 73; t++) wsum[wid][t] = acc[t];
    }
    __syncthreads();
    if (threadIdx.x < 73) {
        float s = 0.f;
#pragma unroll
        for (int w = 0; w < GNT / 32; w++) s += wsum[w][threadIdx.x];
        g_partial[role][threadIdx.x][b] = s;
    }

    // --- deterministic block reduction of S (fp64 tree) ---
    __shared__ double red[GNT];
    red[threadIdx.x] = (double)S;
    __syncthreads();
    for (int o = GNT / 2; o > 0; o >>= 1) {
        if (threadIdx.x < (unsigned)o) red[threadIdx.x] += red[threadIdx.x + o];
        __syncthreads();
    }
    if (threadIdx.x == 0) g_S[role][b] = red[0];
}

// ============================================================================
// Parallel reduction: 148 blocks (frozen from R11 passer)
// ============================================================================
__global__ void __launch_bounds__(256)
rmi_reduce(void) {
    int row = blockIdx.x, t = threadIdx.x;
    __shared__ double red[256];
    double s = 0.0;
    if (row < 146) {
        int role = row >= 73 ? 1 : 0;
        int p = role ? row - 73 : row;
        const float* src = &g_partial[role][p][0];
        for (int bb = t; bb < HALFB; bb += 256) s += (double)__ldg(src + bb);
    } else {
        int role = row - 146;
        for (int bb = t; bb < HALFB; bb += 256) s += g_S[role][bb];
    }
    red[t] = s;
    __syncthreads();
    for (int o = 128; o > 0; o >>= 1) {
        if (t < o) red[t] += red[t + o];
        __syncthreads();
    }
    if (t == 0) {
        if (row < 146) {
            int role = row >= 73 ? 1 : 0;
            int p = role ? row - 73 : row;
            g_G[role][p] = red[0];
        } else {
            g_Stot[row - 146] = red[0];
        }
    }
}

// ============================================================================
// Adam + loss (frozen)
// ============================================================================
__global__ void __launch_bounds__(128)
rmi_adam(int step, float bc1, float bc2, double logN) {
    double S1 = g_Stot[0], S2 = g_Stot[1];
    if (threadIdx.x == 0) {
        double t1 = log(S1) - logN;              // lse(f1) - logN
        double t2 = 0.5 * (log(S2) - logN);      // (lse(f2) - logN)/ALPHA
        g_losses[step] = (float)(t1 - t2);
    }
    if (threadIdx.x < 73) {
        int t = threadIdx.x;
        float g = (float)(g_G[1][t] / S2 - g_G[0][t] / S1);
        float m = 0.9f   * g_m[t] + 0.1f   * g;
        float v = 0.999f * g_v[t] + 0.001f * g * g;
        g_m[t] = m; g_v[t] = v;
        g_P[t] -= 1e-3f * (m / bc1) / (sqrtf(v / bc2) + 1e-8f);
    }
}

__global__ void rmi_write_out(float* __restrict__ out, int out_size) {
    for (int i = threadIdx.x; i < out_size; i += blockDim.x) {
        float v;
        if (out_size == NSTEPS)      v = g_losses[i];
        else if (out_size == 1)      v = g_losses[NSTEPS - 1];
        else {
            if (i == 0)              v = g_losses[NSTEPS - 1];
            else if (i <= NSTEPS)    v = g_losses[i - 1];
            else                     v = 0.f;
        }
        out[i] = v;
    }
}

// ============================================================================
// Host driver (graph-capturable: plain kernel launches only)
// ============================================================================
extern "C" void kernel_launch(void* const* d_in, const int* in_sizes, int n_in,
                              void* d_out, int out_size) {
    const float* x  = (const float*)d_in[0];
    const float* y  = (const float*)d_in[1];
    const float* w1 = (const float*)d_in[2];
    const float* b1 = (const float*)d_in[3];
    const float* w2 = (const float*)d_in[4];
    const float* b2 = (const float*)d_in[5];
    int N = in_sizes[0] / 8;
    if (N > MAXN) N = MAXN;

    // --- shuffle subkeys (host, input-independent, deterministic) ---
    // master key(42) = (0,42); fold-like split: key_s = tf(master,(0,s));
    // per round: new_key = tf(K,(0,0)), subkey = tf(K,(0,1)). 2 rounds for
    // N ~ 1M (ceil(3*log(N)/log(2^32)) = 2).
    SubKeys subk[2];
    for (int s = 0; s < NSEG; s++) {
        unsigned K0, K1;
        tf2x32(0u, 42u, 0u, (unsigned)s, K0, K1);
        for (int r = 0; r < 2; r++) {
            unsigned nk0, nk1, sb0, sb1;
            tf2x32(K0, K1, 0u, 0u, nk0, nk1);
            tf2x32(K0, K1, 0u, 1u, sb0, sb1);
            subk[r].k0[s] = sb0; subk[r].k1[s] = sb1;
            K0 = nk0; K1 = nk1;
        }
    }

    unsigned *v1p, *pp;
    cudaGetSymbolAddress((void**)&v1p, g_v1);
    cudaGetSymbolAddress((void**)&pp, g_perms);

    // --- launches: index 3 == bucket_sort<0> (the profiler's capture slot) ---
    const int cps = (N + CHUNK - 1) / CHUNK;
    rmi_init_zero<<<64, 512>>>(w1, b1, w2, b2);                 // 0
    rmi_scatter<<<NSEG * cps, SCAT_T>>>(subk[0], N, cps, 0);    // 1
    rmi_scan<<<NSEG, 1024>>>(N, 0);                             // 2
    rmi_bucket_sort<0><<<NSEG << BBITS, SORT_T>>>(N, v1p);      // 3  <- profiled
    rmi_scatter<<<NSEG * cps, SCAT_T>>>(subk[1], N, cps, 1);    // 4
    rmi_scan<<<NSEG, 1024>>>(N, 1);                             // 5
    rmi_bucket_sort<1><<<NSEG << BBITS, SORT_T>>>(N, pp);       // 6

    // --- 8 fused training steps ---
    const double logN = log((double)N);
    for (int s = 0; s < NSTEPS; s++) {
        const unsigned* pi = pp + (size_t)s * N;
        rmi_fused_step<<<2 * HALFB, GNT>>>(x, y, pi, N);
        rmi_reduce<<<148, 256>>>();
        double t = (double)(s + 1);
        float bc1 = (float)(1.0 - pow(0.9,   t));
        float bc2 = (float)(1.0 - pow(0.999, t));
        rmi_adam<<<1, 128>>>(s, bc1, bc2, logN);
    }

    rmi_write_out<<<1, 32>>>((float*)d_out, out_size);
}